// round 4
// baseline (speedup 1.0000x reference)
#include <cuda_runtime.h>
#include <math.h>

// ---------------- problem constants ----------------
#define Bsz   4
#define Lsz   2048
#define DMsz  1024
#define EDsz  2048
#define SEGsz 256
#define NSEG  8
#define NLsz  2
#define DTRsz 64
#define DCsz  66   // DTR + N

// ---------------- scratch (static device allocations) ----------------
__device__ float g_xn   [(size_t)Bsz*Lsz*DMsz];
__device__ float g_xz   [(size_t)Bsz*Lsz*2*EDsz];
__device__ float g_xs   [(size_t)Bsz*Lsz*EDsz];
__device__ float g_delta[(size_t)Bsz*Lsz*EDsz];
__device__ float g_dC   [(size_t)Bsz*Lsz*DCsz];
__device__ float g_y    [(size_t)Bsz*Lsz*EDsz];
__device__ float g_K    [(size_t)Bsz*SEGsz*EDsz];
__device__ float g_Kerr [(size_t)Bsz*SEGsz*EDsz];
__device__ float g_h1   [(size_t)Bsz*SEGsz*3*EDsz];
__device__ float g_h2   [(size_t)Bsz*SEGsz*EDsz];
__device__ float g_h3   [(size_t)Bsz*SEGsz*EDsz];
__device__ float g_Xf   [(size_t)Bsz*2*SEGsz*EDsz];
__device__ float g_Zb   [(size_t)Bsz*2*SEGsz*EDsz];
__device__ float g_Yf   [(size_t)Bsz*SEGsz*EDsz];
__device__ float g_dft1 [2*SEGsz*SEGsz];   // [512][256]: rows 0..255 cos, 256..511 -sin
__device__ float g_dft2 [SEGsz*2*SEGsz];   // [256][512]: [cos | -sin] / 256

// ---------------- helpers ----------------
__device__ __forceinline__ float blkSum(float v) {
    __shared__ float sh[32];
    __syncthreads();                      // protect sh reuse across calls
    int lane = threadIdx.x & 31, w = threadIdx.x >> 5;
#pragma unroll
    for (int o = 16; o; o >>= 1) v += __shfl_down_sync(0xffffffffu, v, o);
    if (!lane) sh[w] = v;
    __syncthreads();
    if (w == 0) {
        v = (lane < (int)(blockDim.x >> 5)) ? sh[lane] : 0.f;
#pragma unroll
        for (int o = 16; o; o >>= 1) v += __shfl_down_sync(0xffffffffu, v, o);
        if (!lane) sh[0] = v;
    }
    __syncthreads();
    return sh[0];
}

// ---------------- DFT table init ----------------
__global__ void dft_init_k() {
    int idx = blockIdx.x * 256 + threadIdx.x;   // 65536 threads: (k,t) pairs k,t in [0,256)
    int t = idx & 255, k = idx >> 8;
    int p = (k * t) & 255;
    float ang = 6.283185307179586f * (float)p * (1.0f / 256.0f);
    float s, c;
    sincosf(ang, &s, &c);
    g_dft1[k * 256 + t]         = c;
    g_dft1[(k + 256) * 256 + t] = -s;
    g_dft2[t * 512 + k]         = c  * (1.0f / 256.0f);
    g_dft2[t * 512 + 256 + k]   = -s * (1.0f / 256.0f);
}

// ---------------- RMSNorm ----------------
__global__ void rmsnorm_k(const float* __restrict__ h, const float* __restrict__ w,
                          float* __restrict__ o) {
    size_t base = (size_t)blockIdx.x * DMsz;
    float s = 0.f;
    for (int d = threadIdx.x; d < DMsz; d += 256) { float v = h[base + d]; s += v * v; }
    s = blkSum(s);
    float r = rsqrtf(s * (1.0f / DMsz) + 1e-5f);
    for (int d = threadIdx.x; d < DMsz; d += 256)
        o[base + d] = h[base + d] * r * w[d];
}

// ---------------- fused double depthwise conv (k=2) + SiLU ----------------
__global__ void conv_silu_k(const float* __restrict__ xz,
                            const float* __restrict__ c1w, const float* __restrict__ c1b,
                            const float* __restrict__ c2w, const float* __restrict__ c2b,
                            float* __restrict__ xs) {
    size_t idx = (size_t)blockIdx.x * 256 + threadIdx.x;   // over B*L*ED
    int e = idx & (EDsz - 1);
    int l = (int)((idx >> 11) & (Lsz - 1));
    int b = (int)(idx >> 22);
    const float* base = xz + (size_t)(b * Lsz) * (2 * EDsz) + e;
    float x2 = base[(size_t)l * (2 * EDsz)];
    float x1 = (l >= 1) ? base[(size_t)(l - 1) * (2 * EDsz)] : 0.f;
    float x0 = (l >= 2) ? base[(size_t)(l - 2) * (2 * EDsz)] : 0.f;
    float w10 = c1w[e * 2], w11 = c1w[e * 2 + 1];
    float w20 = c2w[e * 2], w21 = c2w[e * 2 + 1];
    float b1 = c1b[e], b2 = c2b[e];
    float y1a = (l >= 1) ? (b1 + x0 * w10 + x1 * w11) : 0.f;   // y1(l-1), padded 0 at l=0
    float y1b = b1 + x1 * w10 + x2 * w11;                      // y1(l)
    float y2 = b2 + y1a * w20 + y1b * w21;
    xs[idx] = y2 / (1.f + __expf(-y2));
}

// ---------------- generic tiled SGEMM: C = A(MxK) * op(B), NT: B=(NxK), NN: B=(KxN) ----
// EPI: 0 none, 1 bias+relu, 2 relu, 3 bias+softplus, 4 C += result
template<int EPI, bool NT>
__global__ __launch_bounds__(256) void gemm_k(
    const float* __restrict__ A, int lda, long long sA,
    const float* __restrict__ Bm, int ldb, long long sB,
    float* __restrict__ C, int ldc, long long sC,
    int M, int N, int K, const float* __restrict__ bias)
{
    __shared__ float As[16][128];
    __shared__ float Bs[16][132];
    const int bz = blockIdx.z;
    A  += (long long)bz * sA;
    Bm += (long long)bz * sB;
    C  += (long long)bz * sC;
    const int m0 = blockIdx.y * 128, n0 = blockIdx.x * 128;
    const int tid = threadIdx.x;
    const int tx = tid & 15, ty = tid >> 4;
    float acc[8][8];
#pragma unroll
    for (int i = 0; i < 8; i++)
#pragma unroll
        for (int j = 0; j < 8; j++) acc[i][j] = 0.f;

    const bool a4 = ((lda & 3) == 0);
    const bool b4 = ((ldb & 3) == 0);

    for (int k0 = 0; k0 < K; k0 += 16) {
        {   // A tile (transpose on load) — M is always a multiple of 128 here
            int r = tid >> 2, c4 = (tid & 3) << 2;
#pragma unroll
            for (int rr = 0; rr < 2; rr++) {
                int row = r + rr * 64;
                const float* p = A + (long long)(m0 + row) * lda + (k0 + c4);
                float4 v;
                if (a4) v = *(const float4*)p;
                else { v.x = p[0]; v.y = p[1]; v.z = p[2]; v.w = p[3]; }
                As[c4 + 0][row] = v.x; As[c4 + 1][row] = v.y;
                As[c4 + 2][row] = v.z; As[c4 + 3][row] = v.w;
            }
        }
        if (NT) {
            int r = tid >> 2, c4 = (tid & 3) << 2;
#pragma unroll
            for (int rr = 0; rr < 2; rr++) {
                int row = r + rr * 64;
                float4 v = make_float4(0.f, 0.f, 0.f, 0.f);
                if (n0 + row < N) {
                    const float* p = Bm + (long long)(n0 + row) * ldb + (k0 + c4);
                    if (b4) v = *(const float4*)p;
                    else { v.x = p[0]; v.y = p[1]; v.z = p[2]; v.w = p[3]; }
                }
                Bs[c4 + 0][row] = v.x; Bs[c4 + 1][row] = v.y;
                Bs[c4 + 2][row] = v.z; Bs[c4 + 3][row] = v.w;
            }
        } else {
            int r = tid >> 5, c4 = (tid & 31) << 2;
#pragma unroll
            for (int rr = 0; rr < 2; rr++) {
                int kk = r + rr * 8;
                float4 v = make_float4(0.f, 0.f, 0.f, 0.f);
                int n = n0 + c4;
                const float* p = Bm + (long long)(k0 + kk) * ldb + n;
                if (n + 3 < N && b4) v = *(const float4*)p;
                else {
                    if (n < N)     v.x = p[0];
                    if (n + 1 < N) v.y = p[1];
                    if (n + 2 < N) v.z = p[2];
                    if (n + 3 < N) v.w = p[3];
                }
                *(float4*)&Bs[kk][c4] = v;
            }
        }
        __syncthreads();
#pragma unroll
        for (int kk = 0; kk < 16; kk++) {
            float a[8], b[8];
            *(float4*)&a[0] = *(const float4*)&As[kk][ty * 8];
            *(float4*)&a[4] = *(const float4*)&As[kk][ty * 8 + 4];
            *(float4*)&b[0] = *(const float4*)&Bs[kk][tx * 8];
            *(float4*)&b[4] = *(const float4*)&Bs[kk][tx * 8 + 4];
#pragma unroll
            for (int i = 0; i < 8; i++)
#pragma unroll
                for (int j = 0; j < 8; j++)
                    acc[i][j] = fmaf(a[i], b[j], acc[i][j]);
        }
        __syncthreads();
    }
#pragma unroll
    for (int ii = 0; ii < 8; ii++) {
        long long m = m0 + ty * 8 + ii;
        float* Crow = C + m * (long long)ldc;
#pragma unroll
        for (int jj = 0; jj < 8; jj++) {
            int n = n0 + tx * 8 + jj;
            if (n >= N) continue;
            float v = acc[ii][jj];
            if (EPI == 1)      v = fmaxf(v + bias[n], 0.f);
            else if (EPI == 2) v = fmaxf(v, 0.f);
            else if (EPI == 3) { v += bias[n]; v = (v > 20.f) ? v : log1pf(expf(v)); }
            else if (EPI == 4) v += Crow[n];
            Crow[n] = v;
        }
    }
}

// ---------------- zero fill ----------------
__global__ void zero_k(float* p, int n) {
    int i = blockIdx.x * 256 + threadIdx.x;
    if (i < n) p[i] = 0.f;
}

// ---------------- Kerr = softsign((xg - yh)^2) ----------------
__global__ void kerr_k(const float* __restrict__ xs, const float* __restrict__ y,
                       float* __restrict__ Kerr, int s0, int first) {
    size_t idx = (size_t)blockIdx.x * 256 + threadIdx.x;   // B*SEG*ED
    int e = idx & (EDsz - 1);
    int t = (int)((idx >> 11) & (SEGsz - 1));
    int b = (int)(idx >> 19);
    float xg = xs[((size_t)(b * Lsz + s0 + t)) * EDsz + e];
    float yh = first ? 0.f : y[((size_t)(b * Lsz + s0 - SEGsz + t)) * EDsz + e];
    float d = xg - yh; d = d * d;
    Kerr[idx] = d / (1.f + d);
}

// ---------------- LayerNorm(h3) -> Knew; K = (1-a)K + a*Knew ----------------
__global__ void kup_k(const float* __restrict__ h3,
                      const float* __restrict__ lng, const float* __restrict__ lnb,
                      const float* __restrict__ kal, float* __restrict__ K) {
    size_t base = (size_t)blockIdx.x * EDsz;   // row = b*SEG + t
    float v[8];
#pragma unroll
    for (int j = 0; j < 8; j++) v[j] = h3[base + threadIdx.x + j * 256];
    float s = 0.f;
#pragma unroll
    for (int j = 0; j < 8; j++) s += v[j];
    s = blkSum(s);
    float mu = s * (1.0f / EDsz);
    float q = 0.f;
#pragma unroll
    for (int j = 0; j < 8; j++) { float d = v[j] - mu; q += d * d; }
    q = blkSum(q);
    float rstd = rsqrtf(q * (1.0f / EDsz) + 1e-5f);
#pragma unroll
    for (int j = 0; j < 8; j++) {
        int e = threadIdx.x + j * 256;
        float kn = lng[e] * (v[j] - mu) * rstd + lnb[e];
        float a = fminf(fmaxf(kal[e], 0.01f), 0.99f);
        K[base + e] = (1.f - a) * K[base + e] + a * kn;
    }
}

// ---------------- FDU middle: Z = i*c scaling (purely imaginary omega*g) --------
__global__ void czi_k(const float* __restrict__ Xf, const float* __restrict__ delta,
                      float* __restrict__ Z, const float* __restrict__ sigp, int s0) {
    size_t idx = (size_t)blockIdx.x * 256 + threadIdx.x;   // B*SEG*ED
    int e = idx & (EDsz - 1);
    int k = (int)((idx >> 11) & (SEGsz - 1));
    int b = (int)(idx >> 19);
    float sig = sigp[0];
    float f = (float)((k < 128) ? k : k - 256) * (1.0f / 256.0f);
    float gk = __expf(-f * f * sig * sig);
    float dt = delta[((size_t)(b * Lsz + s0 + k)) * EDsz + e];
    float c = 6.283185307179586f * f * gk / (dt + 1e-5f);
    size_t base = ((size_t)b * 2 * SEGsz + k) * EDsz + e;
    float xr = Xf[base];
    float xi = Xf[base + (size_t)SEGsz * EDsz];
    Z[base]                          = -c * xi;
    Z[base + (size_t)SEGsz * EDsz]   =  c * xr;
}

// ---------------- segment scan: emits yh directly (hseg never materialized) ------
__global__ void scan_k(const float* __restrict__ K, const float* __restrict__ delta,
                       const float* __restrict__ xs, const float* __restrict__ Yf,
                       const float* __restrict__ dC, const float* __restrict__ Alog,
                       const float* __restrict__ Dpv, float* __restrict__ y, int s0) {
    int b = blockIdx.x >> 4;                               // ED/128 = 16 chunks
    int e = ((blockIdx.x & 15) << 7) + threadIdx.x;
    float A0 = -__expf(Alog[e * 2 + 0]);
    float A1 = -__expf(Alog[e * 2 + 1]);
    float Dpe = Dpv[e];
    float h0 = 0.f, h1 = 0.f;
    for (int t = 0; t < SEGsz; t++) {
        size_t rL = (size_t)(b * Lsz + s0 + t);
        size_t rS = (size_t)(b * SEGsz + t);
        float Kv  = K[rS * EDsz + e];
        float dg  = delta[rL * EDsz + e];
        float xv  = xs[rL * EDsz + e];
        float Kdy = Kv * Yf[rS * EDsz + e];
        float C0  = __ldg(&dC[rL * DCsz + 64]);
        float C1  = __ldg(&dC[rL * DCsz + 65]);
        {
            float KC = Kv * C0;
            float AmK = A0 * (1.f - KC);
            float Ak  = AmK * (1.f + KC);
            float Bk  = -AmK * Kv;
            float dA  = __expf(dg * Ak);
            h0 = dA * h0 + dg * Bk * xv + Kdy;
        }
        {
            float KC = Kv * C1;
            float AmK = A1 * (1.f - KC);
            float Ak  = AmK * (1.f + KC);
            float Bk  = -AmK * Kv;
            float dA  = __expf(dg * Ak);
            h1 = dA * h1 + dg * Bk * xv + Kdy;
        }
        y[rL * EDsz + e] = h0 * C0 + h1 * C1 + Dpe * xv;
    }
}

// ---------------- gate: y *= silu(z) ----------------
__global__ void gate_k(float* __restrict__ y, const float* __restrict__ xz) {
    size_t idx = (size_t)blockIdx.x * 256 + threadIdx.x;   // B*L*ED
    int e = idx & (EDsz - 1);
    size_t row = idx >> 11;
    float z = xz[row * (2 * EDsz) + EDsz + e];
    float s = z / (1.f + __expf(-z));
    y[idx] *= s;
}

// ---------------- host ----------------
static float* symAddr(const void* sym) {
    void* p = nullptr;
    cudaGetSymbolAddress(&p, sym);
    return (float*)p;
}

extern "C" void kernel_launch(void* const* d_in, const int* in_sizes, int n_in,
                              void* d_out, int out_size) {
    const float* x     = (const float*)d_in[0];
    const float* rms_w = (const float*)d_in[1];
    const float* in_w  = (const float*)d_in[2];
    const float* c1_w  = (const float*)d_in[3];
    const float* c1_b  = (const float*)d_in[4];
    const float* c2_w  = (const float*)d_in[5];
    const float* c2_b  = (const float*)d_in[6];
    const float* xp_w  = (const float*)d_in[7];
    const float* dt_w  = (const float*)d_in[8];
    const float* dt_b  = (const float*)d_in[9];
    const float* A_log = (const float*)d_in[10];
    const float* Dp    = (const float*)d_in[11];
    const float* out_w = (const float*)d_in[12];
    const float* k1_w  = (const float*)d_in[13];
    const float* k1_b  = (const float*)d_in[14];
    const float* k2_w  = (const float*)d_in[15];
    const float* k3_w  = (const float*)d_in[16];
    const float* ln_g  = (const float*)d_in[17];
    const float* ln_b  = (const float*)d_in[18];
    const float* k_al  = (const float*)d_in[19];
    const float* sigma = (const float*)d_in[20];

    float* xn    = symAddr(g_xn);
    float* xz    = symAddr(g_xz);
    float* xs    = symAddr(g_xs);
    float* delta = symAddr(g_delta);
    float* dC    = symAddr(g_dC);
    float* y     = symAddr(g_y);
    float* K     = symAddr(g_K);
    float* Kerr  = symAddr(g_Kerr);
    float* h1    = symAddr(g_h1);
    float* h2    = symAddr(g_h2);
    float* h3    = symAddr(g_h3);
    float* Xf    = symAddr(g_Xf);
    float* Zb    = symAddr(g_Zb);
    float* Yf    = symAddr(g_Yf);
    float* dft1  = symAddr(g_dft1);
    float* dft2  = symAddr(g_dft2);
    float* h = (float*)d_out;

    const int MROWS = Bsz * Lsz;              // 8192
    const int SROWS = Bsz * SEGsz;            // 1024
    const long long SBX = (long long)Lsz * EDsz;
    const long long SBZ = (long long)2 * SEGsz * EDsz;
    const long long SCY = (long long)SEGsz * EDsz;

    dft_init_k<<<256, 256>>>();
    cudaMemcpyAsync(h, x, sizeof(float) * (size_t)MROWS * DMsz, cudaMemcpyDeviceToDevice);

    for (int i = 0; i < NLsz; i++) {
        const float* rms = rms_w + (size_t)i * DMsz;
        const float* inw = in_w  + (size_t)i * 2 * EDsz * DMsz;
        const float* w1c = c1_w + (size_t)i * EDsz * 2;
        const float* b1c = c1_b + (size_t)i * EDsz;
        const float* w2c = c2_w + (size_t)i * EDsz * 2;
        const float* b2c = c2_b + (size_t)i * EDsz;
        const float* xpw = xp_w + (size_t)i * DCsz * EDsz;
        const float* dtw = dt_w + (size_t)i * EDsz * DTRsz;
        const float* dtb = dt_b + (size_t)i * EDsz;
        const float* alg = A_log + (size_t)i * EDsz * 2;
        const float* dpp = Dp + (size_t)i * EDsz;
        const float* ow  = out_w + (size_t)i * DMsz * EDsz;
        const float* k1w = k1_w + (size_t)i * 3 * EDsz * EDsz;
        const float* k1b = k1_b + (size_t)i * 3 * EDsz;
        const float* k2w = k2_w + (size_t)i * EDsz * 3 * EDsz;
        const float* k3w = k3_w + (size_t)i * EDsz * EDsz;
        const float* lng = ln_g + (size_t)i * EDsz;
        const float* lnb = ln_b + (size_t)i * EDsz;
        const float* kal = k_al + (size_t)i * EDsz;
        const float* sig = sigma + i;

        rmsnorm_k<<<MROWS, 256>>>(h, rms, xn);

        // xz = xn @ in_w^T   (8192 x 4096, K=1024)
        gemm_k<0, true><<<dim3(32, 64, 1), 256>>>(xn, DMsz, 0, inw, DMsz, 0,
                                                  xz, 2 * EDsz, 0, MROWS, 2 * EDsz, DMsz, nullptr);

        conv_silu_k<<<(MROWS * EDsz) / 256, 256>>>(xz, w1c, b1c, w2c, b2c, xs);

        // dC = xs @ xp_w^T   (8192 x 66, K=2048)
        gemm_k<0, true><<<dim3(1, 64, 1), 256>>>(xs, EDsz, 0, xpw, EDsz, 0,
                                                 dC, DCsz, 0, MROWS, DCsz, EDsz, nullptr);

        // delta = softplus(dr @ dt_w^T + dt_b)   (8192 x 2048, K=64, lda=66)
        gemm_k<3, true><<<dim3(16, 64, 1), 256>>>(dC, DCsz, 0, dtw, DTRsz, 0,
                                                  delta, EDsz, 0, MROWS, EDsz, DTRsz, dtb);

        zero_k<<<(SROWS * EDsz) / 256, 256>>>(K, SROWS * EDsz);

        for (int s = 0; s < NSEG; s++) {
            int s0 = s * SEGsz;

            kerr_k<<<(SROWS * EDsz) / 256, 256>>>(xs, y, Kerr, s0, s == 0 ? 1 : 0);

            // kproj: h1 = relu(Kerr @ k1_w^T + k1_b)  (1024 x 6144, K=2048)
            gemm_k<1, true><<<dim3(48, 8, 1), 256>>>(Kerr, EDsz, 0, k1w, EDsz, 0,
                                                     h1, 3 * EDsz, 0, SROWS, 3 * EDsz, EDsz, k1b);
            // h2 = relu(h1 @ k2_w^T)                  (1024 x 2048, K=6144)
            gemm_k<2, true><<<dim3(16, 8, 1), 256>>>(h1, 3 * EDsz, 0, k2w, 3 * EDsz, 0,
                                                     h2, EDsz, 0, SROWS, EDsz, 3 * EDsz, nullptr);
            // h3 = h2 @ k3_w^T                        (1024 x 2048, K=2048)
            gemm_k<0, true><<<dim3(16, 8, 1), 256>>>(h2, EDsz, 0, k3w, EDsz, 0,
                                                     h3, EDsz, 0, SROWS, EDsz, EDsz, nullptr);

            kup_k<<<SROWS, 256>>>(h3, lng, lnb, kal, K);

            // FDU stage 1: [Xr; Xi] = [cos; -sin] @ xg   (512 x 2048, K=256, batch=B)
            gemm_k<0, false><<<dim3(16, 4, Bsz), 256>>>(dft1, SEGsz, 0,
                                                        xs + (size_t)s0 * EDsz, EDsz, SBX,
                                                        Xf, EDsz, SBZ, 2 * SEGsz, EDsz, SEGsz, nullptr);
            czi_k<<<(SROWS * EDsz) / 256, 256>>>(Xf, delta, Zb, sig, s0);
            // FDU stage 2: Y = [cos | -sin]/T @ [Zr; Zi]  (256 x 2048, K=512, batch=B)
            gemm_k<0, false><<<dim3(16, 2, Bsz), 256>>>(dft2, 2 * SEGsz, 0,
                                                        Zb, EDsz, SBZ,
                                                        Yf, EDsz, SCY, SEGsz, EDsz, 2 * SEGsz, nullptr);

            scan_k<<<Bsz * (EDsz / 128), 128>>>(K, delta, xs, Yf, dC, alg, dpp, y, s0);
        }

        gate_k<<<(MROWS * EDsz) / 256, 256>>>(y, xz);

        // h += (y*silu(z)) @ out_w^T   (8192 x 1024, K=2048)
        gemm_k<4, true><<<dim3(8, 64, 1), 256>>>(y, EDsz, 0, ow, EDsz, 0,
                                                 h, DMsz, 0, MROWS, DMsz, EDsz, nullptr);
    }
}

// round 6
// speedup vs baseline: 2.4023x; 2.4023x over previous
#include <cuda_runtime.h>
#include <cuda_bf16.h>
#include <math.h>
#include <stdint.h>

// ---------------- problem constants ----------------
#define Bsz   4
#define Lsz   2048
#define DMsz  1024
#define EDsz  2048
#define SEGsz 256
#define NSEG  8
#define NLsz  2
#define DTRsz 64
#define DCsz  66   // DTR + N

// ---------------- scratch (static device allocations) ----------------
__device__ float g_xn   [(size_t)Bsz*Lsz*DMsz];
__device__ float g_xz   [(size_t)Bsz*Lsz*2*EDsz];
__device__ float g_xs   [(size_t)Bsz*Lsz*EDsz];
__device__ float g_delta[(size_t)Bsz*Lsz*EDsz];
__device__ float g_dC   [(size_t)Bsz*Lsz*DCsz];
__device__ float g_y    [(size_t)Bsz*Lsz*EDsz];
__device__ float g_K    [(size_t)Bsz*SEGsz*EDsz];
__device__ float g_Kerr [(size_t)Bsz*SEGsz*EDsz];
__device__ float g_h1   [(size_t)Bsz*SEGsz*3*EDsz];
__device__ float g_h2   [(size_t)Bsz*SEGsz*EDsz];
__device__ float g_h3   [(size_t)Bsz*SEGsz*EDsz];
__device__ float g_Xf   [(size_t)Bsz*2*SEGsz*EDsz];
__device__ float g_Zb   [(size_t)Bsz*2*SEGsz*EDsz];
__device__ float g_Yf   [(size_t)Bsz*SEGsz*EDsz];
__device__ float g_dft1 [2*SEGsz*SEGsz];   // [512][256]: rows 0..255 cos, 256..511 -sin
__device__ float g_dft2 [SEGsz*2*SEGsz];   // [256][512]: [cos | -sin] / 256

// ---------------- helpers ----------------
__device__ __forceinline__ float blkSum(float v) {
    __shared__ float sh[32];
    __syncthreads();
    int lane = threadIdx.x & 31, w = threadIdx.x >> 5;
#pragma unroll
    for (int o = 16; o; o >>= 1) v += __shfl_down_sync(0xffffffffu, v, o);
    if (!lane) sh[w] = v;
    __syncthreads();
    if (w == 0) {
        v = (lane < (int)(blockDim.x >> 5)) ? sh[lane] : 0.f;
#pragma unroll
        for (int o = 16; o; o >>= 1) v += __shfl_down_sync(0xffffffffu, v, o);
        if (!lane) sh[0] = v;
    }
    __syncthreads();
    return sh[0];
}

// ---------------- DFT table init ----------------
__global__ void dft_init_k() {
    int idx = blockIdx.x * 256 + threadIdx.x;
    int t = idx & 255, k = idx >> 8;
    int p = (k * t) & 255;
    float ang = 6.283185307179586f * (float)p * (1.0f / 256.0f);
    float s, c;
    sincosf(ang, &s, &c);
    g_dft1[k * 256 + t]         = c;
    g_dft1[(k + 256) * 256 + t] = -s;
    g_dft2[t * 512 + k]         = c  * (1.0f / 256.0f);
    g_dft2[t * 512 + 256 + k]   = -s * (1.0f / 256.0f);
}

// ---------------- RMSNorm ----------------
__global__ void rmsnorm_k(const float* __restrict__ h, const float* __restrict__ w,
                          float* __restrict__ o) {
    size_t base = (size_t)blockIdx.x * DMsz;
    float s = 0.f;
    for (int d = threadIdx.x; d < DMsz; d += 256) { float v = h[base + d]; s += v * v; }
    s = blkSum(s);
    float r = rsqrtf(s * (1.0f / DMsz) + 1e-5f);
    for (int d = threadIdx.x; d < DMsz; d += 256)
        o[base + d] = h[base + d] * r * w[d];
}

// ---------------- fused double depthwise conv (k=2) + SiLU ----------------
__global__ void conv_silu_k(const float* __restrict__ xz,
                            const float* __restrict__ c1w, const float* __restrict__ c1b,
                            const float* __restrict__ c2w, const float* __restrict__ c2b,
                            float* __restrict__ xs) {
    size_t idx = (size_t)blockIdx.x * 256 + threadIdx.x;
    int e = idx & (EDsz - 1);
    int l = (int)((idx >> 11) & (Lsz - 1));
    int b = (int)(idx >> 22);
    const float* base = xz + (size_t)(b * Lsz) * (2 * EDsz) + e;
    float x2 = base[(size_t)l * (2 * EDsz)];
    float x1 = (l >= 1) ? base[(size_t)(l - 1) * (2 * EDsz)] : 0.f;
    float x0 = (l >= 2) ? base[(size_t)(l - 2) * (2 * EDsz)] : 0.f;
    float w10 = c1w[e * 2], w11 = c1w[e * 2 + 1];
    float w20 = c2w[e * 2], w21 = c2w[e * 2 + 1];
    float b1 = c1b[e], b2 = c2b[e];
    float y1a = (l >= 1) ? (b1 + x0 * w10 + x1 * w11) : 0.f;
    float y1b = b1 + x1 * w10 + x2 * w11;
    float y2 = b2 + y1a * w20 + y1b * w21;
    xs[idx] = y2 / (1.f + __expf(-y2));
}

// ================= tensor-core split-bf16 GEMM =================
// C = A(MxK) * op(B).  NT: B is N x K row-major.  NN: B is K x N row-major.
// All M,N multiples of 128; K multiple of 32.  No bounds checks.
// EPI: 0 none, 1 bias+relu, 2 relu, 4 C += result
__device__ __forceinline__ void mma16816(float* d, const uint32_t* a, uint32_t b0, uint32_t b1) {
    asm volatile(
        "mma.sync.aligned.m16n8k16.row.col.f32.bf16.bf16.f32 "
        "{%0,%1,%2,%3}, {%4,%5,%6,%7}, {%8,%9}, {%0,%1,%2,%3};\n"
        : "+f"(d[0]), "+f"(d[1]), "+f"(d[2]), "+f"(d[3])
        : "r"(a[0]), "r"(a[1]), "r"(a[2]), "r"(a[3]), "r"(b0), "r"(b1));
}
__device__ __forceinline__ void ldsm4(uint32_t* r, uint32_t addr) {
    asm volatile("ldmatrix.sync.aligned.m8n8.x4.shared.b16 {%0,%1,%2,%3}, [%4];\n"
        : "=r"(r[0]), "=r"(r[1]), "=r"(r[2]), "=r"(r[3]) : "r"(addr));
}
__device__ __forceinline__ __nv_bfloat162 split_hi(float a, float b,
                                                   float& ra, float& rb) {
    __nv_bfloat16 ha = __float2bfloat16(a), hb = __float2bfloat16(b);
    ra = a - __bfloat162float(ha);
    rb = b - __bfloat162float(hb);
    return __halves2bfloat162(ha, hb);
}

template<int EPI, bool NT>
__global__ __launch_bounds__(256) void tgemm_k(
    const float* __restrict__ A, int lda, long long sA,
    const float* __restrict__ Bm, int ldb, long long sB,
    float* __restrict__ C, int ldc, long long sC,
    int K, const float* __restrict__ bias)
{
    // padded stride 40 halves = 80 bytes: 80*i mod 128 cycles all 8 16B banks.
    __shared__ __align__(16) __nv_bfloat16 Ah[128][40];
    __shared__ __align__(16) __nv_bfloat16 Al[128][40];
    __shared__ __align__(16) __nv_bfloat16 Bh[128][40];
    __shared__ __align__(16) __nv_bfloat16 Bl[128][40];

    const int bz = blockIdx.z;
    A  += (long long)bz * sA;
    Bm += (long long)bz * sB;
    C  += (long long)bz * sC;
    const int m0 = blockIdx.y * 128, n0 = blockIdx.x * 128;
    const int tid = threadIdx.x;
    const int lane = tid & 31, wid = tid >> 5;
    const int wm = wid & 1, wn = wid >> 1;   // warp grid 2(m) x 4(n), warp tile 64x32

    float acc[4][4][4];
#pragma unroll
    for (int i = 0; i < 4; i++)
#pragma unroll
        for (int j = 0; j < 4; j++)
#pragma unroll
            for (int q = 0; q < 4; q++) acc[i][j][q] = 0.f;

    const int ak4 = tid & 7;      // float4 column within 32-float k-tile
    const int ar0 = tid >> 3;     // base row (0..31), rows ar0+32i
    const int bn4 = tid & 31;     // NN: float4 column along n
    const int bk0 = tid >> 5;     // NN: base k row (0..7), rows bk0+8i

    float4 av[4], bv[4];

    auto loadTile = [&](int k0) {
        const float* pa = A + (long long)(m0 + ar0) * lda + k0 + ak4 * 4;
#pragma unroll
        for (int i = 0; i < 4; i++) av[i] = *(const float4*)(pa + (long long)(32 * i) * lda);
        if (NT) {
            const float* pb = Bm + (long long)(n0 + ar0) * ldb + k0 + ak4 * 4;
#pragma unroll
            for (int i = 0; i < 4; i++) bv[i] = *(const float4*)(pb + (long long)(32 * i) * ldb);
        } else {
            const float* pb = Bm + (long long)(k0 + bk0) * ldb + n0 + bn4 * 4;
#pragma unroll
            for (int i = 0; i < 4; i++) bv[i] = *(const float4*)(pb + (long long)(8 * i) * ldb);
        }
    };

    auto storeTile = [&]() {
#pragma unroll
        for (int i = 0; i < 4; i++) {
            int row = ar0 + 32 * i;
            float4 v = av[i];
            float r0, r1, r2, r3;
            __nv_bfloat162 h01 = split_hi(v.x, v.y, r0, r1);
            __nv_bfloat162 h23 = split_hi(v.z, v.w, r2, r3);
            __nv_bfloat162* dh = (__nv_bfloat162*)&Ah[row][ak4 * 4];
            dh[0] = h01; dh[1] = h23;
            __nv_bfloat162* dl = (__nv_bfloat162*)&Al[row][ak4 * 4];
            dl[0] = __halves2bfloat162(__float2bfloat16(r0), __float2bfloat16(r1));
            dl[1] = __halves2bfloat162(__float2bfloat16(r2), __float2bfloat16(r3));
        }
        if (NT) {
#pragma unroll
            for (int i = 0; i < 4; i++) {
                int row = ar0 + 32 * i;
                float4 v = bv[i];
                float r0, r1, r2, r3;
                __nv_bfloat162 h01 = split_hi(v.x, v.y, r0, r1);
                __nv_bfloat162 h23 = split_hi(v.z, v.w, r2, r3);
                __nv_bfloat162* dh = (__nv_bfloat162*)&Bh[row][ak4 * 4];
                dh[0] = h01; dh[1] = h23;
                __nv_bfloat162* dl = (__nv_bfloat162*)&Bl[row][ak4 * 4];
                dl[0] = __halves2bfloat162(__float2bfloat16(r0), __float2bfloat16(r1));
                dl[1] = __halves2bfloat162(__float2bfloat16(r2), __float2bfloat16(r3));
            }
        } else {
#pragma unroll
            for (int i = 0; i < 4; i++) {
                int kr = bk0 + 8 * i;
                float4 v = bv[i];
                float s4[4] = {v.x, v.y, v.z, v.w};
#pragma unroll
                for (int j = 0; j < 4; j++) {
                    int n = bn4 * 4 + j;
                    __nv_bfloat16 hv = __float2bfloat16(s4[j]);
                    Bh[n][kr] = hv;
                    Bl[n][kr] = __float2bfloat16(s4[j] - __bfloat162float(hv));
                }
            }
        }
    };

    const uint32_t aBaseH = (uint32_t)__cvta_generic_to_shared(&Ah[0][0]);
    const uint32_t aBaseL = (uint32_t)__cvta_generic_to_shared(&Al[0][0]);
    const uint32_t bBaseH = (uint32_t)__cvta_generic_to_shared(&Bh[0][0]);
    const uint32_t bBaseL = (uint32_t)__cvta_generic_to_shared(&Bl[0][0]);
    // ldmatrix source offsets (bytes)
    const uint32_t aOff = ((wm * 64 + (lane & 15)) * 40 + ((lane >> 4) << 3)) * 2;
    const uint32_t bOff = ((wn * 32 + (lane & 7) + ((lane & 16) >> 1)) * 40 + (lane & 8)) * 2;

    const int kt = K >> 5;
    loadTile(0);
    for (int t = 0; t < kt; t++) {
        storeTile();
        __syncthreads();
        if (t + 1 < kt) loadTile((t + 1) << 5);
#pragma unroll
        for (int ks = 0; ks < 2; ks++) {
            uint32_t bhf[2][4], blf[2][4];
#pragma unroll
            for (int nt = 0; nt < 2; nt++) {
                ldsm4(bhf[nt], bBaseH + bOff + nt * 16 * 80 + ks * 32);
                ldsm4(blf[nt], bBaseL + bOff + nt * 16 * 80 + ks * 32);
            }
#pragma unroll
            for (int mt = 0; mt < 4; mt++) {
                uint32_t ahf[4], alf[4];
                ldsm4(ahf, aBaseH + aOff + mt * 16 * 80 + ks * 32);
                ldsm4(alf, aBaseL + aOff + mt * 16 * 80 + ks * 32);
#pragma unroll
                for (int n8 = 0; n8 < 4; n8++) {
                    uint32_t b0h = bhf[n8 >> 1][(n8 & 1) * 2];
                    uint32_t b1h = bhf[n8 >> 1][(n8 & 1) * 2 + 1];
                    uint32_t b0l = blf[n8 >> 1][(n8 & 1) * 2];
                    uint32_t b1l = blf[n8 >> 1][(n8 & 1) * 2 + 1];
                    mma16816(acc[mt][n8], ahf, b0h, b1h);   // hi*hi
                    mma16816(acc[mt][n8], ahf, b0l, b1l);   // hi*lo
                    mma16816(acc[mt][n8], alf, b0h, b1h);   // lo*hi
                }
            }
        }
        __syncthreads();
    }

    // epilogue: c0,c1 -> row g, cols 2c,2c+1 ; c2,c3 -> row g+8
    const int g = lane >> 2, cc = (lane & 3) * 2;
#pragma unroll
    for (int mt = 0; mt < 4; mt++) {
        long long m = m0 + wm * 64 + mt * 16 + g;
#pragma unroll
        for (int n8 = 0; n8 < 4; n8++) {
            int col = n0 + wn * 32 + n8 * 8 + cc;
            float* a4 = acc[mt][n8];
            float2 v0 = make_float2(a4[0], a4[1]);
            float2 v1 = make_float2(a4[2], a4[3]);
            if (EPI == 1) {
                float b0 = bias[col], b1 = bias[col + 1];
                v0.x = fmaxf(v0.x + b0, 0.f); v0.y = fmaxf(v0.y + b1, 0.f);
                v1.x = fmaxf(v1.x + b0, 0.f); v1.y = fmaxf(v1.y + b1, 0.f);
            } else if (EPI == 2) {
                v0.x = fmaxf(v0.x, 0.f); v0.y = fmaxf(v0.y, 0.f);
                v1.x = fmaxf(v1.x, 0.f); v1.y = fmaxf(v1.y, 0.f);
            }
            float* p0 = C + m * ldc + col;
            float* p1 = C + (m + 8) * ldc + col;
            if (EPI == 4) {
                float2 o0 = *(float2*)p0, o1 = *(float2*)p1;
                v0.x += o0.x; v0.y += o0.y; v1.x += o1.x; v1.y += o1.y;
            }
            *(float2*)p0 = v0;
            *(float2*)p1 = v1;
        }
    }
}

// ---------------- SIMT fp32 GEMM (kept for small / precision-critical GEMMs) ---
// EPI: 0 none, 3 bias+softplus
template<int EPI>
__global__ __launch_bounds__(256) void gemm_k(
    const float* __restrict__ A, int lda,
    const float* __restrict__ Bm, int ldb,
    float* __restrict__ C, int ldc,
    int M, int N, int K, const float* __restrict__ bias)
{
    __shared__ float As[16][128];
    __shared__ float Bs[16][132];
    const int m0 = blockIdx.y * 128, n0 = blockIdx.x * 128;
    const int tid = threadIdx.x;
    const int tx = tid & 15, ty = tid >> 4;
    float acc[8][8];
#pragma unroll
    for (int i = 0; i < 8; i++)
#pragma unroll
        for (int j = 0; j < 8; j++) acc[i][j] = 0.f;

    const bool a4 = ((lda & 3) == 0);

    for (int k0 = 0; k0 < K; k0 += 16) {
        {
            int r = tid >> 2, c4 = (tid & 3) << 2;
#pragma unroll
            for (int rr = 0; rr < 2; rr++) {
                int row = r + rr * 64;
                const float* p = A + (long long)(m0 + row) * lda + (k0 + c4);
                float4 v;
                if (a4) v = *(const float4*)p;
                else { v.x = p[0]; v.y = p[1]; v.z = p[2]; v.w = p[3]; }
                As[c4 + 0][row] = v.x; As[c4 + 1][row] = v.y;
                As[c4 + 2][row] = v.z; As[c4 + 3][row] = v.w;
            }
        }
        {
            int r = tid >> 2, c4 = (tid & 3) << 2;
#pragma unroll
            for (int rr = 0; rr < 2; rr++) {
                int row = r + rr * 64;
                float4 v = make_float4(0.f, 0.f, 0.f, 0.f);
                if (n0 + row < N) {
                    const float* p = Bm + (long long)(n0 + row) * ldb + (k0 + c4);
                    v.x = p[0]; v.y = p[1]; v.z = p[2]; v.w = p[3];
                }
                Bs[c4 + 0][row] = v.x; Bs[c4 + 1][row] = v.y;
                Bs[c4 + 2][row] = v.z; Bs[c4 + 3][row] = v.w;
            }
        }
        __syncthreads();
#pragma unroll
        for (int kk = 0; kk < 16; kk++) {
            float a[8], b[8];
            *(float4*)&a[0] = *(const float4*)&As[kk][ty * 8];
            *(float4*)&a[4] = *(const float4*)&As[kk][ty * 8 + 4];
            *(float4*)&b[0] = *(const float4*)&Bs[kk][tx * 8];
            *(float4*)&b[4] = *(const float4*)&Bs[kk][tx * 8 + 4];
#pragma unroll
            for (int i = 0; i < 8; i++)
#pragma unroll
                for (int j = 0; j < 8; j++)
                    acc[i][j] = fmaf(a[i], b[j], acc[i][j]);
        }
        __syncthreads();
    }
#pragma unroll
    for (int ii = 0; ii < 8; ii++) {
        long long m = m0 + ty * 8 + ii;
        float* Crow = C + m * (long long)ldc;
#pragma unroll
        for (int jj = 0; jj < 8; jj++) {
            int n = n0 + tx * 8 + jj;
            if (n >= N) continue;
            float v = acc[ii][jj];
            if (EPI == 3) { v += bias[n]; v = (v > 20.f) ? v : log1pf(expf(v)); }
            Crow[n] = v;
        }
    }
}

// ---------------- zero fill ----------------
__global__ void zero_k(float* p, int n) {
    int i = blockIdx.x * 256 + threadIdx.x;
    if (i < n) p[i] = 0.f;
}

// ---------------- Kerr = softsign((xg - yh)^2) ----------------
__global__ void kerr_k(const float* __restrict__ xs, const float* __restrict__ y,
                       float* __restrict__ Kerr, int s0, int first) {
    size_t idx = (size_t)blockIdx.x * 256 + threadIdx.x;
    int e = idx & (EDsz - 1);
    int t = (int)((idx >> 11) & (SEGsz - 1));
    int b = (int)(idx >> 19);
    float xg = xs[((size_t)(b * Lsz + s0 + t)) * EDsz + e];
    float yh = first ? 0.f : y[((size_t)(b * Lsz + s0 - SEGsz + t)) * EDsz + e];
    float d = xg - yh; d = d * d;
    Kerr[idx] = d / (1.f + d);
}

// ---------------- LayerNorm(h3) -> Knew; K = (1-a)K + a*Knew ----------------
__global__ void kup_k(const float* __restrict__ h3,
                      const float* __restrict__ lng, const float* __restrict__ lnb,
                      const float* __restrict__ kal, float* __restrict__ K) {
    size_t base = (size_t)blockIdx.x * EDsz;
    float v[8];
#pragma unroll
    for (int j = 0; j < 8; j++) v[j] = h3[base + threadIdx.x + j * 256];
    float s = 0.f;
#pragma unroll
    for (int j = 0; j < 8; j++) s += v[j];
    s = blkSum(s);
    float mu = s * (1.0f / EDsz);
    float q = 0.f;
#pragma unroll
    for (int j = 0; j < 8; j++) { float d = v[j] - mu; q += d * d; }
    q = blkSum(q);
    float rstd = rsqrtf(q * (1.0f / EDsz) + 1e-5f);
#pragma unroll
    for (int j = 0; j < 8; j++) {
        int e = threadIdx.x + j * 256;
        float kn = lng[e] * (v[j] - mu) * rstd + lnb[e];
        float a = fminf(fmaxf(kal[e], 0.01f), 0.99f);
        K[base + e] = (1.f - a) * K[base + e] + a * kn;
    }
}

// ---------------- FDU middle: Z = i*c scaling ----------------
__global__ void czi_k(const float* __restrict__ Xf, const float* __restrict__ delta,
                      float* __restrict__ Z, const float* __restrict__ sigp, int s0) {
    size_t idx = (size_t)blockIdx.x * 256 + threadIdx.x;
    int e = idx & (EDsz - 1);
    int k = (int)((idx >> 11) & (SEGsz - 1));
    int b = (int)(idx >> 19);
    float sig = sigp[0];
    float f = (float)((k < 128) ? k : k - 256) * (1.0f / 256.0f);
    float gk = __expf(-f * f * sig * sig);
    float dt = delta[((size_t)(b * Lsz + s0 + k)) * EDsz + e];
    float c = 6.283185307179586f * f * gk / (dt + 1e-5f);
    size_t base = ((size_t)b * 2 * SEGsz + k) * EDsz + e;
    float xr = Xf[base];
    float xi = Xf[base + (size_t)SEGsz * EDsz];
    Z[base]                        = -c * xi;
    Z[base + (size_t)SEGsz * EDsz] =  c * xr;
}

// ---------------- segment scan ----------------
__global__ void scan_k(const float* __restrict__ K, const float* __restrict__ delta,
                       const float* __restrict__ xs, const float* __restrict__ Yf,
                       const float* __restrict__ dC, const float* __restrict__ Alog,
                       const float* __restrict__ Dpv, float* __restrict__ y, int s0) {
    int b = blockIdx.x >> 4;
    int e = ((blockIdx.x & 15) << 7) + threadIdx.x;
    float A0 = -__expf(Alog[e * 2 + 0]);
    float A1 = -__expf(Alog[e * 2 + 1]);
    float Dpe = Dpv[e];
    float h0 = 0.f, h1 = 0.f;
    for (int t = 0; t < SEGsz; t++) {
        size_t rL = (size_t)(b * Lsz + s0 + t);
        size_t rS = (size_t)(b * SEGsz + t);
        float Kv  = K[rS * EDsz + e];
        float dg  = delta[rL * EDsz + e];
        float xv  = xs[rL * EDsz + e];
        float Kdy = Kv * Yf[rS * EDsz + e];
        float C0  = __ldg(&dC[rL * DCsz + 64]);
        float C1  = __ldg(&dC[rL * DCsz + 65]);
        {
            float KC = Kv * C0;
            float AmK = A0 * (1.f - KC);
            float Ak  = AmK * (1.f + KC);
            float Bk  = -AmK * Kv;
            float dA  = __expf(dg * Ak);
            h0 = dA * h0 + dg * Bk * xv + Kdy;
        }
        {
            float KC = Kv * C1;
            float AmK = A1 * (1.f - KC);
            float Ak  = AmK * (1.f + KC);
            float Bk  = -AmK * Kv;
            float dA  = __expf(dg * Ak);
            h1 = dA * h1 + dg * Bk * xv + Kdy;
        }
        y[rL * EDsz + e] = h0 * C0 + h1 * C1 + Dpe * xv;
    }
}

// ---------------- gate: y *= silu(z) ----------------
__global__ void gate_k(float* __restrict__ y, const float* __restrict__ xz) {
    size_t idx = (size_t)blockIdx.x * 256 + threadIdx.x;
    int e = idx & (EDsz - 1);
    size_t row = idx >> 11;
    float z = xz[row * (2 * EDsz) + EDsz + e];
    float s = z / (1.f + __expf(-z));
    y[idx] *= s;
}

// ---------------- host ----------------
static float* symAddr(const void* sym) {
    void* p = nullptr;
    cudaGetSymbolAddress(&p, sym);
    return (float*)p;
}

extern "C" void kernel_launch(void* const* d_in, const int* in_sizes, int n_in,
                              void* d_out, int out_size) {
    const float* x     = (const float*)d_in[0];
    const float* rms_w = (const float*)d_in[1];
    const float* in_w  = (const float*)d_in[2];
    const float* c1_w  = (const float*)d_in[3];
    const float* c1_b  = (const float*)d_in[4];
    const float* c2_w  = (const float*)d_in[5];
    const float* c2_b  = (const float*)d_in[6];
    const float* xp_w  = (const float*)d_in[7];
    const float* dt_w  = (const float*)d_in[8];
    const float* dt_b  = (const float*)d_in[9];
    const float* A_log = (const float*)d_in[10];
    const float* Dp    = (const float*)d_in[11];
    const float* out_w = (const float*)d_in[12];
    const float* k1_w  = (const float*)d_in[13];
    const float* k1_b  = (const float*)d_in[14];
    const float* k2_w  = (const float*)d_in[15];
    const float* k3_w  = (const float*)d_in[16];
    const float* ln_g  = (const float*)d_in[17];
    const float* ln_b  = (const float*)d_in[18];
    const float* k_al  = (const float*)d_in[19];
    const float* sigma = (const float*)d_in[20];

    float* xn    = symAddr(g_xn);
    float* xz    = symAddr(g_xz);
    float* xs    = symAddr(g_xs);
    float* delta = symAddr(g_delta);
    float* dC    = symAddr(g_dC);
    float* y     = symAddr(g_y);
    float* K     = symAddr(g_K);
    float* Kerr  = symAddr(g_Kerr);
    float* h1    = symAddr(g_h1);
    float* h2    = symAddr(g_h2);
    float* h3    = symAddr(g_h3);
    float* Xf    = symAddr(g_Xf);
    float* Zb    = symAddr(g_Zb);
    float* Yf    = symAddr(g_Yf);
    float* dft1  = symAddr(g_dft1);
    float* dft2  = symAddr(g_dft2);
    float* h = (float*)d_out;

    const int MROWS = Bsz * Lsz;              // 8192
    const int SROWS = Bsz * SEGsz;            // 1024
    const long long SBX = (long long)Lsz * EDsz;
    const long long SBZ = (long long)2 * SEGsz * EDsz;
    const long long SCY = (long long)SEGsz * EDsz;

    dft_init_k<<<256, 256>>>();
    cudaMemcpyAsync(h, x, sizeof(float) * (size_t)MROWS * DMsz, cudaMemcpyDeviceToDevice);

    for (int i = 0; i < NLsz; i++) {
        const float* rms = rms_w + (size_t)i * DMsz;
        const float* inw = in_w  + (size_t)i * 2 * EDsz * DMsz;
        const float* w1c = c1_w + (size_t)i * EDsz * 2;
        const float* b1c = c1_b + (size_t)i * EDsz;
        const float* w2c = c2_w + (size_t)i * EDsz * 2;
        const float* b2c = c2_b + (size_t)i * EDsz;
        const float* xpw = xp_w + (size_t)i * DCsz * EDsz;
        const float* dtw = dt_w + (size_t)i * EDsz * DTRsz;
        const float* dtb = dt_b + (size_t)i * EDsz;
        const float* alg = A_log + (size_t)i * EDsz * 2;
        const float* dpp = Dp + (size_t)i * EDsz;
        const float* ow  = out_w + (size_t)i * DMsz * EDsz;
        const float* k1w = k1_w + (size_t)i * 3 * EDsz * EDsz;
        const float* k1b = k1_b + (size_t)i * 3 * EDsz;
        const float* k2w = k2_w + (size_t)i * EDsz * 3 * EDsz;
        const float* k3w = k3_w + (size_t)i * EDsz * EDsz;
        const float* lng = ln_g + (size_t)i * EDsz;
        const float* lnb = ln_b + (size_t)i * EDsz;
        const float* kal = k_al + (size_t)i * EDsz;
        const float* sig = sigma + i;

        rmsnorm_k<<<MROWS, 256>>>(h, rms, xn);

        // xz = xn @ in_w^T   (8192 x 4096, K=1024)  [tensor]
        tgemm_k<0, true><<<dim3(32, 64, 1), 256>>>(xn, DMsz, 0, inw, DMsz, 0,
                                                   xz, 2 * EDsz, 0, DMsz, nullptr);

        conv_silu_k<<<(MROWS * EDsz) / 256, 256>>>(xz, w1c, b1c, w2c, b2c, xs);

        // dC = xs @ xp_w^T   (8192 x 66, K=2048)  [fp32 SIMT: precision-critical C]
        gemm_k<0><<<dim3(1, 64, 1), 256>>>(xs, EDsz, xpw, EDsz,
                                           dC, DCsz, MROWS, DCsz, EDsz, nullptr);

        // delta = softplus(dr @ dt_w^T + dt_b)   (8192 x 2048, K=64)  [fp32 SIMT]
        gemm_k<3><<<dim3(16, 64, 1), 256>>>(dC, DCsz, dtw, DTRsz,
                                            delta, EDsz, MROWS, EDsz, DTRsz, dtb);

        zero_k<<<(SROWS * EDsz) / 256, 256>>>(K, SROWS * EDsz);

        for (int s = 0; s < NSEG; s++) {
            int s0 = s * SEGsz;

            kerr_k<<<(SROWS * EDsz) / 256, 256>>>(xs, y, Kerr, s0, s == 0 ? 1 : 0);

            // kproj: h1 = relu(Kerr @ k1_w^T + k1_b)  (1024 x 6144, K=2048)
            tgemm_k<1, true><<<dim3(48, 8, 1), 256>>>(Kerr, EDsz, 0, k1w, EDsz, 0,
                                                      h1, 3 * EDsz, 0, EDsz, k1b);
            // h2 = relu(h1 @ k2_w^T)                  (1024 x 2048, K=6144)
            tgemm_k<2, true><<<dim3(16, 8, 1), 256>>>(h1, 3 * EDsz, 0, k2w, 3 * EDsz, 0,
                                                      h2, EDsz, 0, 3 * EDsz, nullptr);
            // h3 = h2 @ k3_w^T                        (1024 x 2048, K=2048)
            tgemm_k<0, true><<<dim3(16, 8, 1), 256>>>(h2, EDsz, 0, k3w, EDsz, 0,
                                                      h3, EDsz, 0, EDsz, nullptr);

            kup_k<<<SROWS, 256>>>(h3, lng, lnb, kal, K);

            // FDU stage 1: [Xr; Xi] = [cos; -sin] @ xg   (512 x 2048, K=256, batch=B)
            tgemm_k<0, false><<<dim3(16, 4, Bsz), 256>>>(dft1, SEGsz, 0,
                                                         xs + (size_t)s0 * EDsz, EDsz, SBX,
                                                         Xf, EDsz, SBZ, SEGsz, nullptr);
            czi_k<<<(SROWS * EDsz) / 256, 256>>>(Xf, delta, Zb, sig, s0);
            // FDU stage 2: Y = [cos | -sin]/T @ [Zr; Zi]  (256 x 2048, K=512, batch=B)
            tgemm_k<0, false><<<dim3(16, 2, Bsz), 256>>>(dft2, 2 * SEGsz, 0,
                                                         Zb, EDsz, SBZ,
                                                         Yf, EDsz, SCY, 2 * SEGsz, nullptr);

            scan_k<<<Bsz * (EDsz / 128), 128>>>(K, delta, xs, Yf, dC, alg, dpp, y, s0);
        }

        gate_k<<<(MROWS * EDsz) / 256, 256>>>(y, xz);

        // h += (y*silu(z)) @ out_w^T   (8192 x 1024, K=2048)  [tensor, accumulate]
        tgemm_k<4, true><<<dim3(8, 64, 1), 256>>>(y, EDsz, 0, ow, EDsz, 0,
                                                  h, DMsz, 0, EDsz, nullptr);
    }
}

// round 8
// speedup vs baseline: 2.6561x; 1.1056x over previous
#include <cuda_runtime.h>
#include <cuda_bf16.h>
#include <math.h>
#include <stdint.h>

// ---------------- problem constants ----------------
#define Bsz   4
#define Lsz   2048
#define DMsz  1024
#define EDsz  2048
#define SEGsz 256
#define NSEG  8
#define NLsz  2
#define DTRsz 64
#define DCsz  66   // DTR + N

// ---------------- fp32 scratch ----------------
__device__ float g_xz   [(size_t)Bsz*Lsz*2*EDsz];
__device__ float g_xs   [(size_t)Bsz*Lsz*EDsz];
__device__ float g_delta[(size_t)Bsz*Lsz*EDsz];
__device__ float g_dC   [(size_t)Bsz*Lsz*DCsz];
__device__ float g_y    [(size_t)Bsz*Lsz*EDsz];
__device__ float g_K    [(size_t)Bsz*SEGsz*EDsz];
__device__ float g_h3   [(size_t)Bsz*SEGsz*EDsz];
__device__ float g_Xf   [(size_t)Bsz*2*SEGsz*EDsz];
__device__ float g_Zb   [(size_t)Bsz*2*SEGsz*EDsz];
__device__ float g_Yf   [(size_t)Bsz*SEGsz*EDsz];
__device__ float g_dft1 [2*SEGsz*SEGsz];
__device__ float g_dft2 [SEGsz*2*SEGsz];

// ---------------- bf16 split pairs ----------------
__device__ __nv_bfloat16 g_xnh [(size_t)Bsz*Lsz*DMsz],      g_xnl [(size_t)Bsz*Lsz*DMsz];
__device__ __nv_bfloat16 g_inwh[(size_t)2*EDsz*DMsz],       g_inwl[(size_t)2*EDsz*DMsz];
__device__ __nv_bfloat16 g_xsh [(size_t)Bsz*Lsz*EDsz],      g_xsl [(size_t)Bsz*Lsz*EDsz];
__device__ __nv_bfloat16 g_xpwh[(size_t)128*EDsz],          g_xpwl[(size_t)128*EDsz];
__device__ __nv_bfloat16 g_keh [(size_t)Bsz*SEGsz*EDsz],    g_kel [(size_t)Bsz*SEGsz*EDsz];
__device__ __nv_bfloat16 g_k1wh[(size_t)3*EDsz*EDsz],       g_k1wl[(size_t)3*EDsz*EDsz];
__device__ __nv_bfloat16 g_h1h [(size_t)Bsz*SEGsz*3*EDsz],  g_h1l [(size_t)Bsz*SEGsz*3*EDsz];
__device__ __nv_bfloat16 g_k2wh[(size_t)EDsz*3*EDsz],       g_k2wl[(size_t)EDsz*3*EDsz];
__device__ __nv_bfloat16 g_h2h [(size_t)Bsz*SEGsz*EDsz],    g_h2l [(size_t)Bsz*SEGsz*EDsz];
__device__ __nv_bfloat16 g_k3wh[(size_t)EDsz*EDsz],         g_k3wl[(size_t)EDsz*EDsz];
__device__ __nv_bfloat16 g_ygh [(size_t)Bsz*Lsz*EDsz],      g_ygl [(size_t)Bsz*Lsz*EDsz];
__device__ __nv_bfloat16 g_owh [(size_t)DMsz*EDsz],         g_owl [(size_t)DMsz*EDsz];

// ---------------- small helpers ----------------
__device__ __forceinline__ void fsplit(float v, __nv_bfloat16& h, __nv_bfloat16& l) {
    h = __float2bfloat16(v);
    l = __float2bfloat16(v - __bfloat162float(h));
}
__device__ __forceinline__ float blkSum(float v) {
    __shared__ float sh[32];
    __syncthreads();
    int lane = threadIdx.x & 31, w = threadIdx.x >> 5;
#pragma unroll
    for (int o = 16; o; o >>= 1) v += __shfl_down_sync(0xffffffffu, v, o);
    if (!lane) sh[w] = v;
    __syncthreads();
    if (w == 0) {
        v = (lane < (int)(blockDim.x >> 5)) ? sh[lane] : 0.f;
#pragma unroll
        for (int o = 16; o; o >>= 1) v += __shfl_down_sync(0xffffffffu, v, o);
        if (!lane) sh[0] = v;
    }
    __syncthreads();
    return sh[0];
}

// ---------------- mma / async primitives ----------------
__device__ __forceinline__ void mma16816(float* d, const uint32_t* a, uint32_t b0, uint32_t b1) {
    asm volatile(
        "mma.sync.aligned.m16n8k16.row.col.f32.bf16.bf16.f32 "
        "{%0,%1,%2,%3}, {%4,%5,%6,%7}, {%8,%9}, {%0,%1,%2,%3};\n"
        : "+f"(d[0]), "+f"(d[1]), "+f"(d[2]), "+f"(d[3])
        : "r"(a[0]), "r"(a[1]), "r"(a[2]), "r"(a[3]), "r"(b0), "r"(b1));
}
__device__ __forceinline__ void ldsm4(uint32_t* r, uint32_t addr) {
    asm volatile("ldmatrix.sync.aligned.m8n8.x4.shared.b16 {%0,%1,%2,%3}, [%4];\n"
        : "=r"(r[0]), "=r"(r[1]), "=r"(r[2]), "=r"(r[3]) : "r"(addr));
}
__device__ __forceinline__ void cpa16(uint32_t dst, const void* src) {
    asm volatile("cp.async.cg.shared.global [%0], [%1], 16;\n" :: "r"(dst), "l"(src));
}
__device__ __forceinline__ void cpa_commit() { asm volatile("cp.async.commit_group;\n" ::: "memory"); }
template<int N> __device__ __forceinline__ void cpa_wait() {
    asm volatile("cp.async.wait_group %0;\n" :: "n"(N) : "memory");
}

// ================= pre-split bf16 mma.sync GEMM =================
// D = A(MxK) @ B(NxK)^T, split-3: AhBh + AhBl + AlBh, fp32 accum.
// A,B given as bf16 hi/lo pair arrays. M,N mult of 128 (store guarded by Nn), K mult of 32.
// EPI: 0 none, 1 bias+relu, 2 relu, 4 C += result.  PAIR: emit bf16 hi/lo output.
#define TS_STAGE 32768   // Ah,Al,Bh,Bl @ 8KB each (128 rows x 64B)
#define TS_DSMEM (2*TS_STAGE)
template<int EPI, bool PAIR>
__global__ __launch_bounds__(256) void ts_gemm_k(
    const __nv_bfloat16* __restrict__ Ahg, const __nv_bfloat16* __restrict__ Alg,
    const __nv_bfloat16* __restrict__ Bhg, const __nv_bfloat16* __restrict__ Blg,
    float* __restrict__ C, __nv_bfloat16* __restrict__ Oh, __nv_bfloat16* __restrict__ Ol,
    int lda, int ldb, int ldc, int Nn, int K, const float* __restrict__ bias)
{
    extern __shared__ char sm[];
    const int tid = threadIdx.x;
    const int lane = tid & 31, wid = tid >> 5;
    const int wm = wid & 1, wn = wid >> 1;          // 2(m) x 4(n) warps, warp tile 64x32
    const int m0 = blockIdx.y * 128, n0 = blockIdx.x * 128;

    float acc[4][4][4];
#pragma unroll
    for (int i = 0; i < 4; i++)
#pragma unroll
        for (int j = 0; j < 4; j++)
#pragma unroll
            for (int q = 0; q < 4; q++) acc[i][j][q] = 0.f;

    const uint32_t smBase = (uint32_t)__cvta_generic_to_shared(sm);

    // fill: each matrix is 128 rows x 32 halves (64B). 512 x 16B chunks, 2/thread.
    const int frow0 = tid >> 2;          // rows frow0, frow0+64
    const int fc    = tid & 3;           // 16B chunk in row
    auto fill = [&](int k0, int st) {
        const uint32_t base = smBase + st * TS_STAGE;
#pragma unroll
        for (int i = 0; i < 2; i++) {
            int row = frow0 + i * 64;
            uint32_t off = (uint32_t)(row * 64 + fc * 16);
            uint32_t dsw = off ^ ((off >> 3) & 0x30);
            const __nv_bfloat16* pah = Ahg + (size_t)(m0 + row) * lda + k0 + fc * 8;
            const __nv_bfloat16* pal = Alg + (size_t)(m0 + row) * lda + k0 + fc * 8;
            const __nv_bfloat16* pbh = Bhg + (size_t)(n0 + row) * ldb + k0 + fc * 8;
            const __nv_bfloat16* pbl = Blg + (size_t)(n0 + row) * ldb + k0 + fc * 8;
            cpa16(base +         dsw, pah);
            cpa16(base +  8192 + dsw, pal);
            cpa16(base + 16384 + dsw, pbh);
            cpa16(base + 24576 + dsw, pbl);
        }
        cpa_commit();
    };

    // ldmatrix source addresses (swizzled), within a stage base
    const int aRow = wm * 64 + (lane & 15);              // + mt*16
    const int aCh  = (lane >> 4);                        // + ks*2
    const int bRow = wn * 32 + (lane & 7) + ((lane & 16) >> 1);   // + nt2*16
    const int bCh  = ((lane & 8) >> 3);                  // + ks*2

    const int kt = K >> 5;
    fill(0, 0);
    for (int t = 0; t < kt; t++) {
        if (t + 1 < kt) { fill((t + 1) << 5, (t + 1) & 1); cpa_wait<1>(); }
        else            { cpa_wait<0>(); }
        __syncthreads();
        const uint32_t base = smBase + (t & 1) * TS_STAGE;
#pragma unroll
        for (int ks = 0; ks < 2; ks++) {
            uint32_t bh[2][4], bl[2][4];
#pragma unroll
            for (int nt2 = 0; nt2 < 2; nt2++) {
                uint32_t off = (uint32_t)((bRow + nt2 * 16) * 64 + (bCh + ks * 2) * 16);
                uint32_t dsw = off ^ ((off >> 3) & 0x30);
                ldsm4(bh[nt2], base + 16384 + dsw);
                ldsm4(bl[nt2], base + 24576 + dsw);
            }
#pragma unroll
            for (int mt = 0; mt < 4; mt++) {
                uint32_t off = (uint32_t)((aRow + mt * 16) * 64 + (aCh + ks * 2) * 16);
                uint32_t dsw = off ^ ((off >> 3) & 0x30);
                uint32_t ah[4], al[4];
                ldsm4(ah, base + dsw);
                ldsm4(al, base + 8192 + dsw);
#pragma unroll
                for (int n8 = 0; n8 < 4; n8++) {
                    uint32_t b0h = bh[n8 >> 1][(n8 & 1) * 2];
                    uint32_t b1h = bh[n8 >> 1][(n8 & 1) * 2 + 1];
                    uint32_t b0l = bl[n8 >> 1][(n8 & 1) * 2];
                    uint32_t b1l = bl[n8 >> 1][(n8 & 1) * 2 + 1];
                    mma16816(acc[mt][n8], ah, b0h, b1h);
                    mma16816(acc[mt][n8], ah, b0l, b1l);
                    mma16816(acc[mt][n8], al, b0h, b1h);
                }
            }
        }
        __syncthreads();
    }

    // epilogue: c0,c1 -> row g cols cc,cc+1 ; c2,c3 -> row g+8
    const int g = lane >> 2, cc = (lane & 3) * 2;
#pragma unroll
    for (int mt = 0; mt < 4; mt++) {
        long long m = m0 + wm * 64 + mt * 16 + g;
#pragma unroll
        for (int n8 = 0; n8 < 4; n8++) {
            int col = n0 + wn * 32 + n8 * 8 + cc;
            if (col >= Nn) continue;
            float* a4 = acc[mt][n8];
            float2 v0 = make_float2(a4[0], a4[1]);
            float2 v1 = make_float2(a4[2], a4[3]);
            if (EPI == 1) {
                float b0 = bias[col], b1 = bias[col + 1];
                v0.x = fmaxf(v0.x + b0, 0.f); v0.y = fmaxf(v0.y + b1, 0.f);
                v1.x = fmaxf(v1.x + b0, 0.f); v1.y = fmaxf(v1.y + b1, 0.f);
            } else if (EPI == 2) {
                v0.x = fmaxf(v0.x, 0.f); v0.y = fmaxf(v0.y, 0.f);
                v1.x = fmaxf(v1.x, 0.f); v1.y = fmaxf(v1.y, 0.f);
            }
            if (PAIR) {
                __nv_bfloat162 h0, l0, h1, l1;
                fsplit(v0.x, h0.x, l0.x); fsplit(v0.y, h0.y, l0.y);
                fsplit(v1.x, h1.x, l1.x); fsplit(v1.y, h1.y, l1.y);
                *(__nv_bfloat162*)(Oh + m * ldc + col)       = h0;
                *(__nv_bfloat162*)(Ol + m * ldc + col)       = l0;
                *(__nv_bfloat162*)(Oh + (m + 8) * ldc + col) = h1;
                *(__nv_bfloat162*)(Ol + (m + 8) * ldc + col) = l1;
            } else {
                float* p0 = C + m * ldc + col;
                float* p1 = C + (m + 8) * ldc + col;
                if (EPI == 4) {
                    float2 o0 = *(float2*)p0, o1 = *(float2*)p1;
                    v0.x += o0.x; v0.y += o0.y; v1.x += o1.x; v1.y += o1.y;
                }
                *(float2*)p0 = v0;
                *(float2*)p1 = v1;
            }
        }
    }
}

// ---------------- DFT table init ----------------
__global__ void dft_init_k() {
    int idx = blockIdx.x * 256 + threadIdx.x;
    int t = idx & 255, k = idx >> 8;
    int p = (k * t) & 255;
    float ang = 6.283185307179586f * (float)p * (1.0f / 256.0f);
    float s, c;
    sincosf(ang, &s, &c);
    g_dft1[k * 256 + t]         = c;
    g_dft1[(k + 256) * 256 + t] = -s;
    g_dft2[t * 512 + k]         = c  * (1.0f / 256.0f);
    g_dft2[t * 512 + 256 + k]   = -s * (1.0f / 256.0f);
}

// ---------------- weight split (fp32 -> bf16 hi/lo) ----------------
__global__ void wsplit_k(const float* __restrict__ src, __nv_bfloat16* __restrict__ dh,
                         __nv_bfloat16* __restrict__ dl, int n) {
    int i = blockIdx.x * 256 + threadIdx.x;
    if (i < n) fsplit(src[i], dh[i], dl[i]);
}
// xp_w padded to 128 rows (rows 66..127 zero)
__global__ void xppad_k(const float* __restrict__ src, __nv_bfloat16* __restrict__ dh,
                        __nv_bfloat16* __restrict__ dl) {
    int i = blockIdx.x * 256 + threadIdx.x;   // 128*2048
    int row = i >> 11;
    float v = (row < DCsz) ? src[(size_t)row * EDsz + (i & (EDsz - 1))] : 0.f;
    fsplit(v, dh[i], dl[i]);
}

// ---------------- RMSNorm -> bf16 pair ----------------
__global__ void rmsnorm_k(const float* __restrict__ h, const float* __restrict__ w,
                          __nv_bfloat16* __restrict__ oh, __nv_bfloat16* __restrict__ ol) {
    size_t base = (size_t)blockIdx.x * DMsz;
    float s = 0.f;
    for (int d = threadIdx.x; d < DMsz; d += 256) { float v = h[base + d]; s += v * v; }
    s = blkSum(s);
    float r = rsqrtf(s * (1.0f / DMsz) + 1e-5f);
    for (int d = threadIdx.x; d < DMsz; d += 256) {
        float v = h[base + d] * r * w[d];
        fsplit(v, oh[base + d], ol[base + d]);
    }
}

// ---------------- fused double depthwise conv (k=2) + SiLU (fp32 + pair out) ----
__global__ void conv_silu_k(const float* __restrict__ xz,
                            const float* __restrict__ c1w, const float* __restrict__ c1b,
                            const float* __restrict__ c2w, const float* __restrict__ c2b,
                            float* __restrict__ xs,
                            __nv_bfloat16* __restrict__ xsh, __nv_bfloat16* __restrict__ xsl) {
    size_t idx = (size_t)blockIdx.x * 256 + threadIdx.x;
    int e = idx & (EDsz - 1);
    int l = (int)((idx >> 11) & (Lsz - 1));
    int b = (int)(idx >> 22);
    const float* base = xz + (size_t)(b * Lsz) * (2 * EDsz) + e;
    float x2 = base[(size_t)l * (2 * EDsz)];
    float x1 = (l >= 1) ? base[(size_t)(l - 1) * (2 * EDsz)] : 0.f;
    float x0 = (l >= 2) ? base[(size_t)(l - 2) * (2 * EDsz)] : 0.f;
    float w10 = c1w[e * 2], w11 = c1w[e * 2 + 1];
    float w20 = c2w[e * 2], w21 = c2w[e * 2 + 1];
    float b1 = c1b[e], b2 = c2b[e];
    float y1a = (l >= 1) ? (b1 + x0 * w10 + x1 * w11) : 0.f;
    float y1b = b1 + x1 * w10 + x2 * w11;
    float y2 = b2 + y1a * w20 + y1b * w21;
    float v = y2 / (1.f + __expf(-y2));
    xs[idx] = v;
    fsplit(v, xsh[idx], xsl[idx]);
}

// ---------------- mma.sync NN GEMM with in-kernel split (FDU only) --------------
__device__ __forceinline__ __nv_bfloat162 split_hi(float a, float b, float& ra, float& rb) {
    __nv_bfloat16 ha = __float2bfloat16(a), hb = __float2bfloat16(b);
    ra = a - __bfloat162float(ha);
    rb = b - __bfloat162float(hb);
    return __halves2bfloat162(ha, hb);
}

__global__ __launch_bounds__(256) void tgemm_nn_k(
    const float* __restrict__ A, int lda, long long sA,
    const float* __restrict__ Bm, int ldb, long long sB,
    float* __restrict__ C, int ldc, long long sC,
    int K)
{
    __shared__ __align__(16) __nv_bfloat16 Ah[128][40];
    __shared__ __align__(16) __nv_bfloat16 Al[128][40];
    __shared__ __align__(16) __nv_bfloat16 Bh[128][40];
    __shared__ __align__(16) __nv_bfloat16 Bl[128][40];

    const int bz = blockIdx.z;
    A  += (long long)bz * sA;
    Bm += (long long)bz * sB;
    C  += (long long)bz * sC;
    const int m0 = blockIdx.y * 128, n0 = blockIdx.x * 128;
    const int tid = threadIdx.x;
    const int lane = tid & 31, wid = tid >> 5;
    const int wm = wid & 1, wn = wid >> 1;

    float acc[4][4][4];
#pragma unroll
    for (int i = 0; i < 4; i++)
#pragma unroll
        for (int j = 0; j < 4; j++)
#pragma unroll
            for (int q = 0; q < 4; q++) acc[i][j][q] = 0.f;

    const int ak4 = tid & 7;
    const int ar0 = tid >> 3;
    const int bn4 = tid & 31;
    const int bk0 = tid >> 5;

    float4 av[4], bv[4];
    auto loadTile = [&](int k0) {
        const float* pa = A + (long long)(m0 + ar0) * lda + k0 + ak4 * 4;
#pragma unroll
        for (int i = 0; i < 4; i++) av[i] = *(const float4*)(pa + (long long)(32 * i) * lda);
        const float* pb = Bm + (long long)(k0 + bk0) * ldb + n0 + bn4 * 4;
#pragma unroll
        for (int i = 0; i < 4; i++) bv[i] = *(const float4*)(pb + (long long)(8 * i) * ldb);
    };
    auto storeTile = [&]() {
#pragma unroll
        for (int i = 0; i < 4; i++) {
            int row = ar0 + 32 * i;
            float4 v = av[i];
            float r0, r1, r2, r3;
            __nv_bfloat162 h01 = split_hi(v.x, v.y, r0, r1);
            __nv_bfloat162 h23 = split_hi(v.z, v.w, r2, r3);
            __nv_bfloat162* dh = (__nv_bfloat162*)&Ah[row][ak4 * 4];
            dh[0] = h01; dh[1] = h23;
            __nv_bfloat162* dl = (__nv_bfloat162*)&Al[row][ak4 * 4];
            dl[0] = __halves2bfloat162(__float2bfloat16(r0), __float2bfloat16(r1));
            dl[1] = __halves2bfloat162(__float2bfloat16(r2), __float2bfloat16(r3));
        }
#pragma unroll
        for (int i = 0; i < 4; i++) {
            int kr = bk0 + 8 * i;
            float4 v = bv[i];
            float s4[4] = {v.x, v.y, v.z, v.w};
#pragma unroll
            for (int j = 0; j < 4; j++) {
                int n = bn4 * 4 + j;
                __nv_bfloat16 hv = __float2bfloat16(s4[j]);
                Bh[n][kr] = hv;
                Bl[n][kr] = __float2bfloat16(s4[j] - __bfloat162float(hv));
            }
        }
    };

    const uint32_t aBaseH = (uint32_t)__cvta_generic_to_shared(&Ah[0][0]);
    const uint32_t aBaseL = (uint32_t)__cvta_generic_to_shared(&Al[0][0]);
    const uint32_t bBaseH = (uint32_t)__cvta_generic_to_shared(&Bh[0][0]);
    const uint32_t bBaseL = (uint32_t)__cvta_generic_to_shared(&Bl[0][0]);
    const uint32_t aOff = ((wm * 64 + (lane & 15)) * 40 + ((lane >> 4) << 3)) * 2;
    const uint32_t bOff = ((wn * 32 + (lane & 7) + ((lane & 16) >> 1)) * 40 + (lane & 8)) * 2;

    const int kt = K >> 5;
    loadTile(0);
    for (int t = 0; t < kt; t++) {
        storeTile();
        __syncthreads();
        if (t + 1 < kt) loadTile((t + 1) << 5);
#pragma unroll
        for (int ks = 0; ks < 2; ks++) {
            uint32_t bhf[2][4], blf[2][4];
#pragma unroll
            for (int nt2 = 0; nt2 < 2; nt2++) {
                ldsm4(bhf[nt2], bBaseH + bOff + nt2 * 16 * 80 + ks * 32);
                ldsm4(blf[nt2], bBaseL + bOff + nt2 * 16 * 80 + ks * 32);
            }
#pragma unroll
            for (int mt = 0; mt < 4; mt++) {
                uint32_t ahf[4], alf[4];
                ldsm4(ahf, aBaseH + aOff + mt * 16 * 80 + ks * 32);
                ldsm4(alf, aBaseL + aOff + mt * 16 * 80 + ks * 32);
#pragma unroll
                for (int n8 = 0; n8 < 4; n8++) {
                    uint32_t b0h = bhf[n8 >> 1][(n8 & 1) * 2];
                    uint32_t b1h = bhf[n8 >> 1][(n8 & 1) * 2 + 1];
                    uint32_t b0l = blf[n8 >> 1][(n8 & 1) * 2];
                    uint32_t b1l = blf[n8 >> 1][(n8 & 1) * 2 + 1];
                    mma16816(acc[mt][n8], ahf, b0h, b1h);
                    mma16816(acc[mt][n8], ahf, b0l, b1l);
                    mma16816(acc[mt][n8], alf, b0h, b1h);
                }
            }
        }
        __syncthreads();
    }

    const int g = lane >> 2, cc = (lane & 3) * 2;
#pragma unroll
    for (int mt = 0; mt < 4; mt++) {
        long long m = m0 + wm * 64 + mt * 16 + g;
#pragma unroll
        for (int n8 = 0; n8 < 4; n8++) {
            int col = n0 + wn * 32 + n8 * 8 + cc;
            float* a4 = acc[mt][n8];
            *(float2*)(C + m * ldc + col)       = make_float2(a4[0], a4[1]);
            *(float2*)(C + (m + 8) * ldc + col) = make_float2(a4[2], a4[3]);
        }
    }
}

// ---------------- SIMT fp32 GEMM (delta only: bias+softplus) ----------------
__global__ __launch_bounds__(256) void gemm_sp_k(
    const float* __restrict__ A, int lda,
    const float* __restrict__ Bm, int ldb,
    float* __restrict__ C, int ldc,
    int N, int K, const float* __restrict__ bias)
{
    __shared__ float As[16][128];
    __shared__ float Bs[16][132];
    const int m0 = blockIdx.y * 128, n0 = blockIdx.x * 128;
    const int tid = threadIdx.x;
    const int tx = tid & 15, ty = tid >> 4;
    float acc[8][8];
#pragma unroll
    for (int i = 0; i < 8; i++)
#pragma unroll
        for (int j = 0; j < 8; j++) acc[i][j] = 0.f;
    const bool a4 = ((lda & 3) == 0);

    for (int k0 = 0; k0 < K; k0 += 16) {
        {
            int r = tid >> 2, c4 = (tid & 3) << 2;
#pragma unroll
            for (int rr = 0; rr < 2; rr++) {
                int row = r + rr * 64;
                const float* p = A + (long long)(m0 + row) * lda + (k0 + c4);
                float4 v;
                if (a4) v = *(const float4*)p;
                else { v.x = p[0]; v.y = p[1]; v.z = p[2]; v.w = p[3]; }
                As[c4 + 0][row] = v.x; As[c4 + 1][row] = v.y;
                As[c4 + 2][row] = v.z; As[c4 + 3][row] = v.w;
            }
        }
        {
            int r = tid >> 2, c4 = (tid & 3) << 2;
#pragma unroll
            for (int rr = 0; rr < 2; rr++) {
                int row = r + rr * 64;
                float4 v = make_float4(0.f, 0.f, 0.f, 0.f);
                if (n0 + row < N) {
                    const float* p = Bm + (long long)(n0 + row) * ldb + (k0 + c4);
                    v.x = p[0]; v.y = p[1]; v.z = p[2]; v.w = p[3];
                }
                Bs[c4 + 0][row] = v.x; Bs[c4 + 1][row] = v.y;
                Bs[c4 + 2][row] = v.z; Bs[c4 + 3][row] = v.w;
            }
        }
        __syncthreads();
#pragma unroll
        for (int kk = 0; kk < 16; kk++) {
            float a[8], b[8];
            *(float4*)&a[0] = *(const float4*)&As[kk][ty * 8];
            *(float4*)&a[4] = *(const float4*)&As[kk][ty * 8 + 4];
            *(float4*)&b[0] = *(const float4*)&Bs[kk][tx * 8];
            *(float4*)&b[4] = *(const float4*)&Bs[kk][tx * 8 + 4];
#pragma unroll
            for (int i = 0; i < 8; i++)
#pragma unroll
                for (int j = 0; j < 8; j++)
                    acc[i][j] = fmaf(a[i], b[j], acc[i][j]);
        }
        __syncthreads();
    }
#pragma unroll
    for (int ii = 0; ii < 8; ii++) {
        long long m = m0 + ty * 8 + ii;
        float* Crow = C + m * (long long)ldc;
#pragma unroll
        for (int jj = 0; jj < 8; jj++) {
            int n = n0 + tx * 8 + jj;
            if (n >= N) continue;
            float v = acc[ii][jj] + bias[n];
            Crow[n] = (v > 20.f) ? v : log1pf(expf(v));
        }
    }
}

// ---------------- zero fill ----------------
__global__ void zero_k(float* p, int n) {
    int i = blockIdx.x * 256 + threadIdx.x;
    if (i < n) p[i] = 0.f;
}

// ---------------- Kerr pair = softsign((xg - yh)^2) ----------------
__global__ void kerr_k(const float* __restrict__ xs, const float* __restrict__ y,
                       __nv_bfloat16* __restrict__ kh, __nv_bfloat16* __restrict__ kl,
                       int s0, int first) {
    size_t idx = (size_t)blockIdx.x * 256 + threadIdx.x;
    int e = idx & (EDsz - 1);
    int t = (int)((idx >> 11) & (SEGsz - 1));
    int b = (int)(idx >> 19);
    float xg = xs[((size_t)(b * Lsz + s0 + t)) * EDsz + e];
    float yh = first ? 0.f : y[((size_t)(b * Lsz + s0 - SEGsz + t)) * EDsz + e];
    float d = xg - yh; d = d * d;
    fsplit(d / (1.f + d), kh[idx], kl[idx]);
}

// ---------------- LayerNorm(h3) -> Knew; K = (1-a)K + a*Knew ----------------
__global__ void kup_k(const float* __restrict__ h3,
                      const float* __restrict__ lng, const float* __restrict__ lnb,
                      const float* __restrict__ kal, float* __restrict__ K) {
    size_t base = (size_t)blockIdx.x * EDsz;
    float v[8];
#pragma unroll
    for (int j = 0; j < 8; j++) v[j] = h3[base + threadIdx.x + j * 256];
    float s = 0.f;
#pragma unroll
    for (int j = 0; j < 8; j++) s += v[j];
    s = blkSum(s);
    float mu = s * (1.0f / EDsz);
    float q = 0.f;
#pragma unroll
    for (int j = 0; j < 8; j++) { float d = v[j] - mu; q += d * d; }
    q = blkSum(q);
    float rstd = rsqrtf(q * (1.0f / EDsz) + 1e-5f);
#pragma unroll
    for (int j = 0; j < 8; j++) {
        int e = threadIdx.x + j * 256;
        float kn = lng[e] * (v[j] - mu) * rstd + lnb[e];
        float a = fminf(fmaxf(kal[e], 0.01f), 0.99f);
        K[base + e] = (1.f - a) * K[base + e] + a * kn;
    }
}

// ---------------- FDU middle: Z = i*c scaling ----------------
__global__ void czi_k(const float* __restrict__ Xf, const float* __restrict__ delta,
                      float* __restrict__ Z, const float* __restrict__ sigp, int s0) {
    size_t idx = (size_t)blockIdx.x * 256 + threadIdx.x;
    int e = idx & (EDsz - 1);
    int k = (int)((idx >> 11) & (SEGsz - 1));
    int b = (int)(idx >> 19);
    float sig = sigp[0];
    float f = (float)((k < 128) ? k : k - 256) * (1.0f / 256.0f);
    float gk = __expf(-f * f * sig * sig);
    float dt = delta[((size_t)(b * Lsz + s0 + k)) * EDsz + e];
    float c = 6.283185307179586f * f * gk / (dt + 1e-5f);
    size_t base = ((size_t)b * 2 * SEGsz + k) * EDsz + e;
    float xr = Xf[base];
    float xi = Xf[base + (size_t)SEGsz * EDsz];
    Z[base]                        = -c * xi;
    Z[base + (size_t)SEGsz * EDsz] =  c * xr;
}

// ---------------- segment scan ----------------
__global__ void scan_k(const float* __restrict__ K, const float* __restrict__ delta,
                       const float* __restrict__ xs, const float* __restrict__ Yf,
                       const float* __restrict__ dC, const float* __restrict__ Alog,
                       const float* __restrict__ Dpv, float* __restrict__ y, int s0) {
    int b = blockIdx.x >> 4;
    int e = ((blockIdx.x & 15) << 7) + threadIdx.x;
    float A0 = -__expf(Alog[e * 2 + 0]);
    float A1 = -__expf(Alog[e * 2 + 1]);
    float Dpe = Dpv[e];
    float h0 = 0.f, h1 = 0.f;
    for (int t = 0; t < SEGsz; t++) {
        size_t rL = (size_t)(b * Lsz + s0 + t);
        size_t rS = (size_t)(b * SEGsz + t);
        float Kv  = K[rS * EDsz + e];
        float dg  = delta[rL * EDsz + e];
        float xv  = xs[rL * EDsz + e];
        float Kdy = Kv * Yf[rS * EDsz + e];
        float C0  = __ldg(&dC[rL * DCsz + 64]);
        float C1  = __ldg(&dC[rL * DCsz + 65]);
        {
            float KC = Kv * C0;
            float AmK = A0 * (1.f - KC);
            float Ak  = AmK * (1.f + KC);
            float Bk  = -AmK * Kv;
            float dA  = __expf(dg * Ak);
            h0 = dA * h0 + dg * Bk * xv + Kdy;
        }
        {
            float KC = Kv * C1;
            float AmK = A1 * (1.f - KC);
            float Ak  = AmK * (1.f + KC);
            float Bk  = -AmK * Kv;
            float dA  = __expf(dg * Ak);
            h1 = dA * h1 + dg * Bk * xv + Kdy;
        }
        y[rL * EDsz + e] = h0 * C0 + h1 * C1 + Dpe * xv;
    }
}

// ---------------- gate: yg = y * silu(z) -> bf16 pair ----------------
__global__ void gate_k(const float* __restrict__ y, const float* __restrict__ xz,
                       __nv_bfloat16* __restrict__ gh, __nv_bfloat16* __restrict__ gl) {
    size_t idx = (size_t)blockIdx.x * 256 + threadIdx.x;
    int e = idx & (EDsz - 1);
    size_t row = idx >> 11;
    float z = xz[row * (2 * EDsz) + EDsz + e];
    float s = z / (1.f + __expf(-z));
    fsplit(y[idx] * s, gh[idx], gl[idx]);
}

// ---------------- host ----------------
static float* symAddr(const void* sym) {
    void* p = nullptr;
    cudaGetSymbolAddress(&p, sym);
    return (float*)p;
}
static __nv_bfloat16* symAddrB(const void* sym) {
    void* p = nullptr;
    cudaGetSymbolAddress(&p, sym);
    return (__nv_bfloat16*)p;
}

extern "C" void kernel_launch(void* const* d_in, const int* in_sizes, int n_in,
                              void* d_out, int out_size) {
    const float* x     = (const float*)d_in[0];
    const float* rms_w = (const float*)d_in[1];
    const float* in_w  = (const float*)d_in[2];
    const float* c1_w  = (const float*)d_in[3];
    const float* c1_b  = (const float*)d_in[4];
    const float* c2_w  = (const float*)d_in[5];
    const float* c2_b  = (const float*)d_in[6];
    const float* xp_w  = (const float*)d_in[7];
    const float* dt_w  = (const float*)d_in[8];
    const float* dt_b  = (const float*)d_in[9];
    const float* A_log = (const float*)d_in[10];
    const float* Dp    = (const float*)d_in[11];
    const float* out_w = (const float*)d_in[12];
    const float* k1_w  = (const float*)d_in[13];
    const float* k1_b  = (const float*)d_in[14];
    const float* k2_w  = (const float*)d_in[15];
    const float* k3_w  = (const float*)d_in[16];
    const float* ln_g  = (const float*)d_in[17];
    const float* ln_b  = (const float*)d_in[18];
    const float* k_al  = (const float*)d_in[19];
    const float* sigma = (const float*)d_in[20];

    float* xz    = symAddr(g_xz);
    float* xs    = symAddr(g_xs);
    float* delta = symAddr(g_delta);
    float* dC    = symAddr(g_dC);
    float* y     = symAddr(g_y);
    float* K     = symAddr(g_K);
    float* h3    = symAddr(g_h3);
    float* Xf    = symAddr(g_Xf);
    float* Zb    = symAddr(g_Zb);
    float* Yf    = symAddr(g_Yf);
    float* dft1  = symAddr(g_dft1);
    float* dft2  = symAddr(g_dft2);
    __nv_bfloat16 *xnh = symAddrB(g_xnh),  *xnl = symAddrB(g_xnl);
    __nv_bfloat16 *inwh= symAddrB(g_inwh), *inwl= symAddrB(g_inwl);
    __nv_bfloat16 *xsh = symAddrB(g_xsh),  *xsl = symAddrB(g_xsl);
    __nv_bfloat16 *xpwh= symAddrB(g_xpwh), *xpwl= symAddrB(g_xpwl);
    __nv_bfloat16 *keh = symAddrB(g_keh),  *kel = symAddrB(g_kel);
    __nv_bfloat16 *k1wh= symAddrB(g_k1wh), *k1wl= symAddrB(g_k1wl);
    __nv_bfloat16 *h1h = symAddrB(g_h1h),  *h1l = symAddrB(g_h1l);
    __nv_bfloat16 *k2wh= symAddrB(g_k2wh), *k2wl= symAddrB(g_k2wl);
    __nv_bfloat16 *h2h = symAddrB(g_h2h),  *h2l = symAddrB(g_h2l);
    __nv_bfloat16 *k3wh= symAddrB(g_k3wh), *k3wl= symAddrB(g_k3wl);
    __nv_bfloat16 *ygh = symAddrB(g_ygh),  *ygl = symAddrB(g_ygl);
    __nv_bfloat16 *owh = symAddrB(g_owh),  *owl = symAddrB(g_owl);
    float* h = (float*)d_out;

    cudaFuncSetAttribute(ts_gemm_k<0,false>, cudaFuncAttributeMaxDynamicSharedMemorySize, TS_DSMEM);
    cudaFuncSetAttribute(ts_gemm_k<1,true>,  cudaFuncAttributeMaxDynamicSharedMemorySize, TS_DSMEM);
    cudaFuncSetAttribute(ts_gemm_k<2,true>,  cudaFuncAttributeMaxDynamicSharedMemorySize, TS_DSMEM);
    cudaFuncSetAttribute(ts_gemm_k<4,false>, cudaFuncAttributeMaxDynamicSharedMemorySize, TS_DSMEM);

    const int MROWS = Bsz * Lsz;              // 8192
    const int SROWS = Bsz * SEGsz;            // 1024
    const long long SBX = (long long)Lsz * EDsz;
    const long long SBZ = (long long)2 * SEGsz * EDsz;
    const long long SCY = (long long)SEGsz * EDsz;

    dft_init_k<<<256, 256>>>();
    cudaMemcpyAsync(h, x, sizeof(float) * (size_t)MROWS * DMsz, cudaMemcpyDeviceToDevice);

    for (int i = 0; i < NLsz; i++) {
        const float* rms = rms_w + (size_t)i * DMsz;
        const float* inw = in_w  + (size_t)i * 2 * EDsz * DMsz;
        const float* w1c = c1_w + (size_t)i * EDsz * 2;
        const float* b1c = c1_b + (size_t)i * EDsz;
        const float* w2c = c2_w + (size_t)i * EDsz * 2;
        const float* b2c = c2_b + (size_t)i * EDsz;
        const float* xpw = xp_w + (size_t)i * DCsz * EDsz;
        const float* dtw = dt_w + (size_t)i * EDsz * DTRsz;
        const float* dtb = dt_b + (size_t)i * EDsz;
        const float* alg = A_log + (size_t)i * EDsz * 2;
        const float* dpp = Dp + (size_t)i * EDsz;
        const float* ow  = out_w + (size_t)i * DMsz * EDsz;
        const float* k1w = k1_w + (size_t)i * 3 * EDsz * EDsz;
        const float* k1b = k1_b + (size_t)i * 3 * EDsz;
        const float* k2w = k2_w + (size_t)i * EDsz * 3 * EDsz;
        const float* k3w = k3_w + (size_t)i * EDsz * EDsz;
        const float* lng = ln_g + (size_t)i * EDsz;
        const float* lnb = ln_b + (size_t)i * EDsz;
        const float* kal = k_al + (size_t)i * EDsz;
        const float* sig = sigma + i;

        // weight splits (once per layer)
        wsplit_k<<<(2*EDsz*DMsz)/256, 256>>>(inw, inwh, inwl, 2*EDsz*DMsz);
        wsplit_k<<<(3*EDsz*EDsz)/256, 256>>>(k1w, k1wh, k1wl, 3*EDsz*EDsz);
        wsplit_k<<<(3*EDsz*EDsz)/256, 256>>>(k2w, k2wh, k2wl, 3*EDsz*EDsz);
        wsplit_k<<<(EDsz*EDsz)/256, 256>>>(k3w, k3wh, k3wl, EDsz*EDsz);
        wsplit_k<<<(DMsz*EDsz)/256, 256>>>(ow, owh, owl, DMsz*EDsz);
        xppad_k<<<(128*EDsz)/256, 256>>>(xpw, xpwh, xpwl);

        rmsnorm_k<<<MROWS, 256>>>(h, rms, xnh, xnl);

        // xz = xn @ in_w^T   (8192 x 4096, K=1024)
        ts_gemm_k<0,false><<<dim3(32, 64), 256, TS_DSMEM>>>(
            xnh, xnl, inwh, inwl, xz, nullptr, nullptr,
            DMsz, DMsz, 2*EDsz, 2*EDsz, DMsz, nullptr);

        conv_silu_k<<<(MROWS * EDsz) / 256, 256>>>(xz, w1c, b1c, w2c, b2c, xs, xsh, xsl);

        // dC = xs @ xp_w^T   (8192 x 66, K=2048) on tensor path via padded xp_w
        ts_gemm_k<0,false><<<dim3(1, 64), 256, TS_DSMEM>>>(
            xsh, xsl, xpwh, xpwl, dC, nullptr, nullptr,
            EDsz, EDsz, DCsz, DCsz, EDsz, nullptr);

        // delta = softplus(dr @ dt_w^T + dt_b)   (8192 x 2048, K=64)  [fp32 SIMT]
        gemm_sp_k<<<dim3(16, 64), 256>>>(dC, DCsz, dtw, DTRsz,
                                         delta, EDsz, EDsz, DTRsz, dtb);

        zero_k<<<(SROWS * EDsz) / 256, 256>>>(K, SROWS * EDsz);

        for (int s = 0; s < NSEG; s++) {
            int s0 = s * SEGsz;

            kerr_k<<<(SROWS * EDsz) / 256, 256>>>(xs, y, keh, kel, s0, s == 0 ? 1 : 0);

            // kproj1: h1 = relu(Kerr @ k1_w^T + b)  (1024 x 6144, K=2048) -> bf16 pair
            ts_gemm_k<1,true><<<dim3(48, 8), 256, TS_DSMEM>>>(
                keh, kel, k1wh, k1wl, nullptr, h1h, h1l,
                EDsz, EDsz, 3*EDsz, 3*EDsz, EDsz, k1b);
            // kproj2: h2 = relu(h1 @ k2_w^T)        (1024 x 2048, K=6144) -> bf16 pair
            ts_gemm_k<2,true><<<dim3(16, 8), 256, TS_DSMEM>>>(
                h1h, h1l, k2wh, k2wl, nullptr, h2h, h2l,
                3*EDsz, 3*EDsz, EDsz, EDsz, 3*EDsz, nullptr);
            // kproj3: h3 = h2 @ k3_w^T              (1024 x 2048, K=2048) -> fp32
            ts_gemm_k<0,false><<<dim3(16, 8), 256, TS_DSMEM>>>(
                h2h, h2l, k3wh, k3wl, h3, nullptr, nullptr,
                EDsz, EDsz, EDsz, EDsz, EDsz, nullptr);

            kup_k<<<SROWS, 256>>>(h3, lng, lnb, kal, K);

            // FDU stage 1: [Xr; Xi] = dft1 @ xg   (512 x 2048, K=256, batch=B)
            tgemm_nn_k<<<dim3(16, 4, Bsz), 256>>>(dft1, SEGsz, 0,
                                                  xs + (size_t)s0 * EDsz, EDsz, SBX,
                                                  Xf, EDsz, SBZ, SEGsz);
            czi_k<<<(SROWS * EDsz) / 256, 256>>>(Xf, delta, Zb, sig, s0);
            // FDU stage 2: Y = dft2 @ [Zr; Zi]    (256 x 2048, K=512, batch=B)
            tgemm_nn_k<<<dim3(16, 2, Bsz), 256>>>(dft2, 2 * SEGsz, 0,
                                                  Zb, EDsz, SBZ,
                                                  Yf, EDsz, SCY, 2 * SEGsz);

            scan_k<<<Bsz * (EDsz / 128), 128>>>(K, delta, xs, Yf, dC, alg, dpp, y, s0);
        }

        gate_k<<<(MROWS * EDsz) / 256, 256>>>(y, xz, ygh, ygl);

        // h += yg @ out_w^T   (8192 x 1024, K=2048)  [accumulate]
        ts_gemm_k<4,false><<<dim3(8, 64), 256, TS_DSMEM>>>(
            ygh, ygl, owh, owl, h, nullptr, nullptr,
            EDsz, EDsz, DMsz, DMsz, EDsz, nullptr);
    }
}

// round 10
// speedup vs baseline: 3.2994x; 1.2422x over previous
#include <cuda_runtime.h>
#include <cuda_fp16.h>
#include <math.h>
#include <stdint.h>

// ---------------- problem constants ----------------
#define Bsz   4
#define Lsz   2048
#define DMsz  1024
#define EDsz  2048
#define SEGsz 256
#define NSEG  8
#define NLsz  2
#define DTRsz 64
#define DCsz  66   // DTR + N

// ---------------- fp32 scratch ----------------
__device__ float g_xz   [(size_t)Bsz*Lsz*2*EDsz];
__device__ float g_xs   [(size_t)Bsz*Lsz*EDsz];
__device__ float g_delta[(size_t)Bsz*Lsz*EDsz];
__device__ float g_dC   [(size_t)Bsz*Lsz*DCsz];
__device__ float g_y    [(size_t)Bsz*Lsz*EDsz];
__device__ float g_K    [(size_t)Bsz*SEGsz*EDsz];
__device__ float g_h3   [(size_t)Bsz*SEGsz*EDsz];
__device__ float g_Xf   [(size_t)Bsz*2*SEGsz*EDsz];
__device__ float g_Zb   [(size_t)Bsz*2*SEGsz*EDsz];
__device__ float g_Yf   [(size_t)Bsz*SEGsz*EDsz];
__device__ float g_dft1 [2*SEGsz*SEGsz];
__device__ float g_dft2 [SEGsz*2*SEGsz];

// ---------------- fp16 operands ----------------
__device__ __half g_xnh [(size_t)Bsz*Lsz*DMsz];
__device__ __half g_inwh[(size_t)2*EDsz*DMsz];
__device__ __half g_xsh [(size_t)Bsz*Lsz*EDsz];
__device__ __half g_xpwh[(size_t)128*EDsz];
__device__ __half g_keh [(size_t)Bsz*SEGsz*EDsz];
__device__ __half g_k1wh[(size_t)3*EDsz*EDsz];
__device__ __half g_h1h [(size_t)Bsz*SEGsz*3*EDsz];
__device__ __half g_k2wh[(size_t)EDsz*3*EDsz];
__device__ __half g_h2h [(size_t)Bsz*SEGsz*EDsz];
__device__ __half g_k3wh[(size_t)EDsz*EDsz];
__device__ __half g_ygh [(size_t)Bsz*Lsz*EDsz];
__device__ __half g_owh [(size_t)DMsz*EDsz];

// ---------------- small helpers ----------------
__device__ __forceinline__ float blkSum(float v) {
    __shared__ float sh[32];
    __syncthreads();
    int lane = threadIdx.x & 31, w = threadIdx.x >> 5;
#pragma unroll
    for (int o = 16; o; o >>= 1) v += __shfl_down_sync(0xffffffffu, v, o);
    if (!lane) sh[w] = v;
    __syncthreads();
    if (w == 0) {
        v = (lane < (int)(blockDim.x >> 5)) ? sh[lane] : 0.f;
#pragma unroll
        for (int o = 16; o; o >>= 1) v += __shfl_down_sync(0xffffffffu, v, o);
        if (!lane) sh[0] = v;
    }
    __syncthreads();
    return sh[0];
}

// ---------------- mma / async primitives ----------------
__device__ __forceinline__ void mma16816(float* d, const uint32_t* a, uint32_t b0, uint32_t b1) {
    asm volatile(
        "mma.sync.aligned.m16n8k16.row.col.f32.f16.f16.f32 "
        "{%0,%1,%2,%3}, {%4,%5,%6,%7}, {%8,%9}, {%0,%1,%2,%3};\n"
        : "+f"(d[0]), "+f"(d[1]), "+f"(d[2]), "+f"(d[3])
        : "r"(a[0]), "r"(a[1]), "r"(a[2]), "r"(a[3]), "r"(b0), "r"(b1));
}
__device__ __forceinline__ void ldsm4(uint32_t* r, uint32_t addr) {
    asm volatile("ldmatrix.sync.aligned.m8n8.x4.shared.b16 {%0,%1,%2,%3}, [%4];\n"
        : "=r"(r[0]), "=r"(r[1]), "=r"(r[2]), "=r"(r[3]) : "r"(addr));
}
__device__ __forceinline__ void cpa16(uint32_t dst, const void* src) {
    asm volatile("cp.async.cg.shared.global [%0], [%1], 16;\n" :: "r"(dst), "l"(src));
}
__device__ __forceinline__ void cpa_commit() { asm volatile("cp.async.commit_group;\n" ::: "memory"); }
template<int N> __device__ __forceinline__ void cpa_wait() {
    asm volatile("cp.async.wait_group %0;\n" :: "n"(N) : "memory");
}

// ================= single-fp16 mma.sync GEMM =================
// D = A(MxK) @ B(NxK)^T, fp16 inputs, fp32 accum.
// M,N mult of 128 (store guarded by Nn), K mult of 32.
// EPI: 0 none, 1 bias+relu, 2 relu, 4 C += result.  PAIR: emit fp16 output.
#define TS_STAGE 16384   // A,B @ 8KB each (128 rows x 64B)
template<int EPI, bool PAIR>
__global__ __launch_bounds__(256) void ts_gemm_k(
    const __half* __restrict__ Ahg, const __half* __restrict__ Bhg,
    float* __restrict__ C, __half* __restrict__ Oh,
    int lda, int ldb, int ldc, int Nn, int K, const float* __restrict__ bias)
{
    __shared__ __align__(16) char sm[2 * TS_STAGE];
    const int tid = threadIdx.x;
    const int lane = tid & 31, wid = tid >> 5;
    const int wm = wid & 1, wn = wid >> 1;          // 2(m) x 4(n) warps, warp tile 64x32
    const int m0 = blockIdx.y * 128, n0 = blockIdx.x * 128;

    float acc[4][4][4];
#pragma unroll
    for (int i = 0; i < 4; i++)
#pragma unroll
        for (int j = 0; j < 4; j++)
#pragma unroll
            for (int q = 0; q < 4; q++) acc[i][j][q] = 0.f;

    const uint32_t smBase = (uint32_t)__cvta_generic_to_shared(sm);

    // fill: each matrix is 128 rows x 32 halves (64B) = 8KB. 2 rows per thread per matrix.
    const int frow0 = tid >> 2;          // rows frow0, frow0+64
    const int fc    = tid & 3;           // 16B chunk in row
    auto fill = [&](int k0, int st) {
        const uint32_t base = smBase + st * TS_STAGE;
#pragma unroll
        for (int i = 0; i < 2; i++) {
            int row = frow0 + i * 64;
            uint32_t off = (uint32_t)(row * 64 + fc * 16);
            uint32_t dsw = off ^ ((off >> 3) & 0x30);
            cpa16(base +        dsw, Ahg + (size_t)(m0 + row) * lda + k0 + fc * 8);
            cpa16(base + 8192 + dsw, Bhg + (size_t)(n0 + row) * ldb + k0 + fc * 8);
        }
        cpa_commit();
    };

    const int aRow = wm * 64 + (lane & 15);              // + mt*16
    const int aCh  = (lane >> 4);                        // + ks*2
    const int bRow = wn * 32 + (lane & 7) + ((lane & 16) >> 1);   // + nt2*16
    const int bCh  = ((lane & 8) >> 3);                  // + ks*2

    const int kt = K >> 5;
    fill(0, 0);
    for (int t = 0; t < kt; t++) {
        if (t + 1 < kt) { fill((t + 1) << 5, (t + 1) & 1); cpa_wait<1>(); }
        else            { cpa_wait<0>(); }
        __syncthreads();
        const uint32_t base = smBase + (t & 1) * TS_STAGE;
#pragma unroll
        for (int ks = 0; ks < 2; ks++) {
            uint32_t bh[2][4];
#pragma unroll
            for (int nt2 = 0; nt2 < 2; nt2++) {
                uint32_t off = (uint32_t)((bRow + nt2 * 16) * 64 + (bCh + ks * 2) * 16);
                uint32_t dsw = off ^ ((off >> 3) & 0x30);
                ldsm4(bh[nt2], base + 8192 + dsw);
            }
#pragma unroll
            for (int mt = 0; mt < 4; mt++) {
                uint32_t off = (uint32_t)((aRow + mt * 16) * 64 + (aCh + ks * 2) * 16);
                uint32_t dsw = off ^ ((off >> 3) & 0x30);
                uint32_t ah[4];
                ldsm4(ah, base + dsw);
#pragma unroll
                for (int n8 = 0; n8 < 4; n8++)
                    mma16816(acc[mt][n8], ah, bh[n8 >> 1][(n8 & 1) * 2], bh[n8 >> 1][(n8 & 1) * 2 + 1]);
            }
        }
        __syncthreads();
    }

    // epilogue: c0,c1 -> row g cols cc,cc+1 ; c2,c3 -> row g+8
    const int g = lane >> 2, cc = (lane & 3) * 2;
#pragma unroll
    for (int mt = 0; mt < 4; mt++) {
        long long m = m0 + wm * 64 + mt * 16 + g;
#pragma unroll
        for (int n8 = 0; n8 < 4; n8++) {
            int col = n0 + wn * 32 + n8 * 8 + cc;
            if (col >= Nn) continue;
            float* a4 = acc[mt][n8];
            float2 v0 = make_float2(a4[0], a4[1]);
            float2 v1 = make_float2(a4[2], a4[3]);
            if (EPI == 1) {
                float b0 = bias[col], b1 = bias[col + 1];
                v0.x = fmaxf(v0.x + b0, 0.f); v0.y = fmaxf(v0.y + b1, 0.f);
                v1.x = fmaxf(v1.x + b0, 0.f); v1.y = fmaxf(v1.y + b1, 0.f);
            } else if (EPI == 2) {
                v0.x = fmaxf(v0.x, 0.f); v0.y = fmaxf(v0.y, 0.f);
                v1.x = fmaxf(v1.x, 0.f); v1.y = fmaxf(v1.y, 0.f);
            }
            if (PAIR) {
                *(__half2*)(Oh + m * ldc + col)       = __floats2half2_rn(v0.x, v0.y);
                *(__half2*)(Oh + (m + 8) * ldc + col) = __floats2half2_rn(v1.x, v1.y);
            } else {
                float* p0 = C + m * ldc + col;
                float* p1 = C + (m + 8) * ldc + col;
                if (EPI == 4) {
                    float2 o0 = *(float2*)p0, o1 = *(float2*)p1;
                    v0.x += o0.x; v0.y += o0.y; v1.x += o1.x; v1.y += o1.y;
                }
                *(float2*)p0 = v0;
                *(float2*)p1 = v1;
            }
        }
    }
}

// ---------------- DFT table init ----------------
__global__ void dft_init_k() {
    int idx = blockIdx.x * 256 + threadIdx.x;
    int t = idx & 255, k = idx >> 8;
    int p = (k * t) & 255;
    float ang = 6.283185307179586f * (float)p * (1.0f / 256.0f);
    float s, c;
    sincosf(ang, &s, &c);
    g_dft1[k * 256 + t]         = c;
    g_dft1[(k + 256) * 256 + t] = -s;
    g_dft2[t * 512 + k]         = c  * (1.0f / 256.0f);
    g_dft2[t * 512 + 256 + k]   = -s * (1.0f / 256.0f);
}

// ---------------- weight convert (fp32 -> fp16) ----------------
__global__ void wconv_k(const float* __restrict__ src, __half* __restrict__ dh, int n) {
    int i = blockIdx.x * 256 + threadIdx.x;
    if (i < n) dh[i] = __float2half_rn(src[i]);
}
// xp_w padded to 128 rows (rows 66..127 zero)
__global__ void xppad_k(const float* __restrict__ src, __half* __restrict__ dh) {
    int i = blockIdx.x * 256 + threadIdx.x;   // 128*2048
    int row = i >> 11;
    float v = (row < DCsz) ? src[(size_t)row * EDsz + (i & (EDsz - 1))] : 0.f;
    dh[i] = __float2half_rn(v);
}

// ---------------- RMSNorm -> fp16 ----------------
__global__ void rmsnorm_k(const float* __restrict__ h, const float* __restrict__ w,
                          __half* __restrict__ oh) {
    size_t base = (size_t)blockIdx.x * DMsz;
    float s = 0.f;
    for (int d = threadIdx.x; d < DMsz; d += 256) { float v = h[base + d]; s += v * v; }
    s = blkSum(s);
    float r = rsqrtf(s * (1.0f / DMsz) + 1e-5f);
    for (int d = threadIdx.x; d < DMsz; d += 256)
        oh[base + d] = __float2half_rn(h[base + d] * r * w[d]);
}

// ---------------- fused double depthwise conv (k=2) + SiLU ----------------
__global__ void conv_silu_k(const float* __restrict__ xz,
                            const float* __restrict__ c1w, const float* __restrict__ c1b,
                            const float* __restrict__ c2w, const float* __restrict__ c2b,
                            float* __restrict__ xs, __half* __restrict__ xsh) {
    size_t idx = (size_t)blockIdx.x * 256 + threadIdx.x;
    int e = idx & (EDsz - 1);
    int l = (int)((idx >> 11) & (Lsz - 1));
    int b = (int)(idx >> 22);
    const float* base = xz + (size_t)(b * Lsz) * (2 * EDsz) + e;
    float x2 = base[(size_t)l * (2 * EDsz)];
    float x1 = (l >= 1) ? base[(size_t)(l - 1) * (2 * EDsz)] : 0.f;
    float x0 = (l >= 2) ? base[(size_t)(l - 2) * (2 * EDsz)] : 0.f;
    float w10 = c1w[e * 2], w11 = c1w[e * 2 + 1];
    float w20 = c2w[e * 2], w21 = c2w[e * 2 + 1];
    float b1 = c1b[e], b2 = c2b[e];
    float y1a = (l >= 1) ? (b1 + x0 * w10 + x1 * w11) : 0.f;
    float y1b = b1 + x1 * w10 + x2 * w11;
    float y2 = b2 + y1a * w20 + y1b * w21;
    float v = y2 / (1.f + __expf(-y2));
    xs[idx] = v;
    xsh[idx] = __float2half_rn(v);
}

// ---------------- fp16 NN GEMM (FDU): C = A(MxK) @ B(KxN), in-kernel convert ----
__global__ __launch_bounds__(256) void tgemm_nn_k(
    const float* __restrict__ A, int lda, long long sA,
    const float* __restrict__ Bm, int ldb, long long sB,
    float* __restrict__ C, int ldc, long long sC,
    int K)
{
    __shared__ __align__(16) __half Ah[128][40];
    __shared__ __align__(16) __half Bh[128][40];

    const int bz = blockIdx.z;
    A  += (long long)bz * sA;
    Bm += (long long)bz * sB;
    C  += (long long)bz * sC;
    const int m0 = blockIdx.y * 128, n0 = blockIdx.x * 128;
    const int tid = threadIdx.x;
    const int lane = tid & 31, wid = tid >> 5;
    const int wm = wid & 1, wn = wid >> 1;

    float acc[4][4][4];
#pragma unroll
    for (int i = 0; i < 4; i++)
#pragma unroll
        for (int j = 0; j < 4; j++)
#pragma unroll
            for (int q = 0; q < 4; q++) acc[i][j][q] = 0.f;

    const int ak4 = tid & 7;
    const int ar0 = tid >> 3;
    const int bn4 = tid & 31;
    const int bk0 = tid >> 5;

    float4 av[4], bv[4];
    auto loadTile = [&](int k0) {
        const float* pa = A + (long long)(m0 + ar0) * lda + k0 + ak4 * 4;
#pragma unroll
        for (int i = 0; i < 4; i++) av[i] = *(const float4*)(pa + (long long)(32 * i) * lda);
        const float* pb = Bm + (long long)(k0 + bk0) * ldb + n0 + bn4 * 4;
#pragma unroll
        for (int i = 0; i < 4; i++) bv[i] = *(const float4*)(pb + (long long)(8 * i) * ldb);
    };
    auto storeTile = [&]() {
#pragma unroll
        for (int i = 0; i < 4; i++) {
            int row = ar0 + 32 * i;
            float4 v = av[i];
            __half2* dh = (__half2*)&Ah[row][ak4 * 4];
            dh[0] = __floats2half2_rn(v.x, v.y);
            dh[1] = __floats2half2_rn(v.z, v.w);
        }
#pragma unroll
        for (int i = 0; i < 4; i++) {
            int kr = bk0 + 8 * i;
            float4 v = bv[i];
            float s4[4] = {v.x, v.y, v.z, v.w};
#pragma unroll
            for (int j = 0; j < 4; j++)
                Bh[bn4 * 4 + j][kr] = __float2half_rn(s4[j]);
        }
    };

    const uint32_t aBase = (uint32_t)__cvta_generic_to_shared(&Ah[0][0]);
    const uint32_t bBase = (uint32_t)__cvta_generic_to_shared(&Bh[0][0]);
    const uint32_t aOff = ((wm * 64 + (lane & 15)) * 40 + ((lane >> 4) << 3)) * 2;
    const uint32_t bOff = ((wn * 32 + (lane & 7) + ((lane & 16) >> 1)) * 40 + (lane & 8)) * 2;

    const int kt = K >> 5;
    loadTile(0);
    for (int t = 0; t < kt; t++) {
        storeTile();
        __syncthreads();
        if (t + 1 < kt) loadTile((t + 1) << 5);
#pragma unroll
        for (int ks = 0; ks < 2; ks++) {
            uint32_t bhf[2][4];
#pragma unroll
            for (int nt2 = 0; nt2 < 2; nt2++)
                ldsm4(bhf[nt2], bBase + bOff + nt2 * 16 * 80 + ks * 32);
#pragma unroll
            for (int mt = 0; mt < 4; mt++) {
                uint32_t ahf[4];
                ldsm4(ahf, aBase + aOff + mt * 16 * 80 + ks * 32);
#pragma unroll
                for (int n8 = 0; n8 < 4; n8++)
                    mma16816(acc[mt][n8], ahf, bhf[n8 >> 1][(n8 & 1) * 2], bhf[n8 >> 1][(n8 & 1) * 2 + 1]);
            }
        }
        __syncthreads();
    }

    const int g = lane >> 2, cc = (lane & 3) * 2;
#pragma unroll
    for (int mt = 0; mt < 4; mt++) {
        long long m = m0 + wm * 64 + mt * 16 + g;
#pragma unroll
        for (int n8 = 0; n8 < 4; n8++) {
            int col = n0 + wn * 32 + n8 * 8 + cc;
            float* a4 = acc[mt][n8];
            *(float2*)(C + m * ldc + col)       = make_float2(a4[0], a4[1]);
            *(float2*)(C + (m + 8) * ldc + col) = make_float2(a4[2], a4[3]);
        }
    }
}

// ---------------- SIMT fp32 GEMM (delta only: bias+softplus) ----------------
__global__ __launch_bounds__(256) void gemm_sp_k(
    const float* __restrict__ A, int lda,
    const float* __restrict__ Bm, int ldb,
    float* __restrict__ C, int ldc,
    int N, int K, const float* __restrict__ bias)
{
    __shared__ float As[16][128];
    __shared__ float Bs[16][132];
    const int m0 = blockIdx.y * 128, n0 = blockIdx.x * 128;
    const int tid = threadIdx.x;
    const int tx = tid & 15, ty = tid >> 4;
    float acc[8][8];
#pragma unroll
    for (int i = 0; i < 8; i++)
#pragma unroll
        for (int j = 0; j < 8; j++) acc[i][j] = 0.f;
    const bool a4 = ((lda & 3) == 0);

    for (int k0 = 0; k0 < K; k0 += 16) {
        {
            int r = tid >> 2, c4 = (tid & 3) << 2;
#pragma unroll
            for (int rr = 0; rr < 2; rr++) {
                int row = r + rr * 64;
                const float* p = A + (long long)(m0 + row) * lda + (k0 + c4);
                float4 v;
                if (a4) v = *(const float4*)p;
                else { v.x = p[0]; v.y = p[1]; v.z = p[2]; v.w = p[3]; }
                As[c4 + 0][row] = v.x; As[c4 + 1][row] = v.y;
                As[c4 + 2][row] = v.z; As[c4 + 3][row] = v.w;
            }
        }
        {
            int r = tid >> 2, c4 = (tid & 3) << 2;
#pragma unroll
            for (int rr = 0; rr < 2; rr++) {
                int row = r + rr * 64;
                float4 v = make_float4(0.f, 0.f, 0.f, 0.f);
                if (n0 + row < N) {
                    const float* p = Bm + (long long)(n0 + row) * ldb + (k0 + c4);
                    v.x = p[0]; v.y = p[1]; v.z = p[2]; v.w = p[3];
                }
                Bs[c4 + 0][row] = v.x; Bs[c4 + 1][row] = v.y;
                Bs[c4 + 2][row] = v.z; Bs[c4 + 3][row] = v.w;
            }
        }
        __syncthreads();
#pragma unroll
        for (int kk = 0; kk < 16; kk++) {
            float a[8], b[8];
            *(float4*)&a[0] = *(const float4*)&As[kk][ty * 8];
            *(float4*)&a[4] = *(const float4*)&As[kk][ty * 8 + 4];
            *(float4*)&b[0] = *(const float4*)&Bs[kk][tx * 8];
            *(float4*)&b[4] = *(const float4*)&Bs[kk][tx * 8 + 4];
#pragma unroll
            for (int i = 0; i < 8; i++)
#pragma unroll
                for (int j = 0; j < 8; j++)
                    acc[i][j] = fmaf(a[i], b[j], acc[i][j]);
        }
        __syncthreads();
    }
#pragma unroll
    for (int ii = 0; ii < 8; ii++) {
        long long m = m0 + ty * 8 + ii;
        float* Crow = C + m * (long long)ldc;
#pragma unroll
        for (int jj = 0; jj < 8; jj++) {
            int n = n0 + tx * 8 + jj;
            if (n >= N) continue;
            float v = acc[ii][jj] + bias[n];
            Crow[n] = (v > 20.f) ? v : log1pf(expf(v));
        }
    }
}

// ---------------- zero fill ----------------
__global__ void zero_k(float* p, int n) {
    int i = blockIdx.x * 256 + threadIdx.x;
    if (i < n) p[i] = 0.f;
}

// ---------------- Kerr = softsign((xg - yh)^2) -> fp16 ----------------
__global__ void kerr_k(const float* __restrict__ xs, const float* __restrict__ y,
                       __half* __restrict__ kh, int s0, int first) {
    size_t idx = (size_t)blockIdx.x * 256 + threadIdx.x;
    int e = idx & (EDsz - 1);
    int t = (int)((idx >> 11) & (SEGsz - 1));
    int b = (int)(idx >> 19);
    float xg = xs[((size_t)(b * Lsz + s0 + t)) * EDsz + e];
    float yh = first ? 0.f : y[((size_t)(b * Lsz + s0 - SEGsz + t)) * EDsz + e];
    float d = xg - yh; d = d * d;
    kh[idx] = __float2half_rn(d / (1.f + d));
}

// ---------------- LayerNorm(h3) -> Knew; K = (1-a)K + a*Knew ----------------
__global__ void kup_k(const float* __restrict__ h3,
                      const float* __restrict__ lng, const float* __restrict__ lnb,
                      const float* __restrict__ kal, float* __restrict__ K) {
    size_t base = (size_t)blockIdx.x * EDsz;
    float v[8];
#pragma unroll
    for (int j = 0; j < 8; j++) v[j] = h3[base + threadIdx.x + j * 256];
    float s = 0.f;
#pragma unroll
    for (int j = 0; j < 8; j++) s += v[j];
    s = blkSum(s);
    float mu = s * (1.0f / EDsz);
    float q = 0.f;
#pragma unroll
    for (int j = 0; j < 8; j++) { float d = v[j] - mu; q += d * d; }
    q = blkSum(q);
    float rstd = rsqrtf(q * (1.0f / EDsz) + 1e-5f);
#pragma unroll
    for (int j = 0; j < 8; j++) {
        int e = threadIdx.x + j * 256;
        float kn = lng[e] * (v[j] - mu) * rstd + lnb[e];
        float a = fminf(fmaxf(kal[e], 0.01f), 0.99f);
        K[base + e] = (1.f - a) * K[base + e] + a * kn;
    }
}

// ---------------- FDU middle: Z = i*c scaling ----------------
__global__ void czi_k(const float* __restrict__ Xf, const float* __restrict__ delta,
                      float* __restrict__ Z, const float* __restrict__ sigp, int s0) {
    size_t idx = (size_t)blockIdx.x * 256 + threadIdx.x;
    int e = idx & (EDsz - 1);
    int k = (int)((idx >> 11) & (SEGsz - 1));
    int b = (int)(idx >> 19);
    float sig = sigp[0];
    float f = (float)((k < 128) ? k : k - 256) * (1.0f / 256.0f);
    float gk = __expf(-f * f * sig * sig);
    float dt = delta[((size_t)(b * Lsz + s0 + k)) * EDsz + e];
    float c = 6.283185307179586f * f * gk / (dt + 1e-5f);
    size_t base = ((size_t)b * 2 * SEGsz + k) * EDsz + e;
    float xr = Xf[base];
    float xi = Xf[base + (size_t)SEGsz * EDsz];
    Z[base]                        = -c * xi;
    Z[base + (size_t)SEGsz * EDsz] =  c * xr;
}

// ---------------- segment scan ----------------
__global__ void scan_k(const float* __restrict__ K, const float* __restrict__ delta,
                       const float* __restrict__ xs, const float* __restrict__ Yf,
                       const float* __restrict__ dC, const float* __restrict__ Alog,
                       const float* __restrict__ Dpv, float* __restrict__ y, int s0) {
    int b = blockIdx.x >> 4;
    int e = ((blockIdx.x & 15) << 7) + threadIdx.x;
    float A0 = -__expf(Alog[e * 2 + 0]);
    float A1 = -__expf(Alog[e * 2 + 1]);
    float Dpe = Dpv[e];
    float h0 = 0.f, h1 = 0.f;
    for (int t = 0; t < SEGsz; t++) {
        size_t rL = (size_t)(b * Lsz + s0 + t);
        size_t rS = (size_t)(b * SEGsz + t);
        float Kv  = K[rS * EDsz + e];
        float dg  = delta[rL * EDsz + e];
        float xv  = xs[rL * EDsz + e];
        float Kdy = Kv * Yf[rS * EDsz + e];
        float C0  = __ldg(&dC[rL * DCsz + 64]);
        float C1  = __ldg(&dC[rL * DCsz + 65]);
        {
            float KC = Kv * C0;
            float AmK = A0 * (1.f - KC);
            float Ak  = AmK * (1.f + KC);
            float Bk  = -AmK * Kv;
            float dA  = __expf(dg * Ak);
            h0 = dA * h0 + dg * Bk * xv + Kdy;
        }
        {
            float KC = Kv * C1;
            float AmK = A1 * (1.f - KC);
            float Ak  = AmK * (1.f + KC);
            float Bk  = -AmK * Kv;
            float dA  = __expf(dg * Ak);
            h1 = dA * h1 + dg * Bk * xv + Kdy;
        }
        y[rL * EDsz + e] = h0 * C0 + h1 * C1 + Dpe * xv;
    }
}

// ---------------- gate: yg = y * silu(z) -> fp16 ----------------
__global__ void gate_k(const float* __restrict__ y, const float* __restrict__ xz,
                       __half* __restrict__ gh) {
    size_t idx = (size_t)blockIdx.x * 256 + threadIdx.x;
    int e = idx & (EDsz - 1);
    size_t row = idx >> 11;
    float z = xz[row * (2 * EDsz) + EDsz + e];
    float s = z / (1.f + __expf(-z));
    gh[idx] = __float2half_rn(y[idx] * s);
}

// ---------------- host ----------------
static float* symAddr(const void* sym) {
    void* p = nullptr;
    cudaGetSymbolAddress(&p, sym);
    return (float*)p;
}
static __half* symAddrH(const void* sym) {
    void* p = nullptr;
    cudaGetSymbolAddress(&p, sym);
    return (__half*)p;
}

extern "C" void kernel_launch(void* const* d_in, const int* in_sizes, int n_in,
                              void* d_out, int out_size) {
    const float* x     = (const float*)d_in[0];
    const float* rms_w = (const float*)d_in[1];
    const float* in_w  = (const float*)d_in[2];
    const float* c1_w  = (const float*)d_in[3];
    const float* c1_b  = (const float*)d_in[4];
    const float* c2_w  = (const float*)d_in[5];
    const float* c2_b  = (const float*)d_in[6];
    const float* xp_w  = (const float*)d_in[7];
    const float* dt_w  = (const float*)d_in[8];
    const float* dt_b  = (const float*)d_in[9];
    const float* A_log = (const float*)d_in[10];
    const float* Dp    = (const float*)d_in[11];
    const float* out_w = (const float*)d_in[12];
    const float* k1_w  = (const float*)d_in[13];
    const float* k1_b  = (const float*)d_in[14];
    const float* k2_w  = (const float*)d_in[15];
    const float* k3_w  = (const float*)d_in[16];
    const float* ln_g  = (const float*)d_in[17];
    const float* ln_b  = (const float*)d_in[18];
    const float* k_al  = (const float*)d_in[19];
    const float* sigma = (const float*)d_in[20];

    float* xz    = symAddr(g_xz);
    float* xs    = symAddr(g_xs);
    float* delta = symAddr(g_delta);
    float* dC    = symAddr(g_dC);
    float* y     = symAddr(g_y);
    float* K     = symAddr(g_K);
    float* h3    = symAddr(g_h3);
    float* Xf    = symAddr(g_Xf);
    float* Zb    = symAddr(g_Zb);
    float* Yf    = symAddr(g_Yf);
    float* dft1  = symAddr(g_dft1);
    float* dft2  = symAddr(g_dft2);
    __half *xnh = symAddrH(g_xnh);
    __half *inwh= symAddrH(g_inwh);
    __half *xsh = symAddrH(g_xsh);
    __half *xpwh= symAddrH(g_xpwh);
    __half *keh = symAddrH(g_keh);
    __half *k1wh= symAddrH(g_k1wh);
    __half *h1h = symAddrH(g_h1h);
    __half *k2wh= symAddrH(g_k2wh);
    __half *h2h = symAddrH(g_h2h);
    __half *k3wh= symAddrH(g_k3wh);
    __half *ygh = symAddrH(g_ygh);
    __half *owh = symAddrH(g_owh);
    float* h = (float*)d_out;

    const int MROWS = Bsz * Lsz;              // 8192
    const int SROWS = Bsz * SEGsz;            // 1024
    const long long SBX = (long long)Lsz * EDsz;
    const long long SBZ = (long long)2 * SEGsz * EDsz;
    const long long SCY = (long long)SEGsz * EDsz;

    dft_init_k<<<256, 256>>>();
    cudaMemcpyAsync(h, x, sizeof(float) * (size_t)MROWS * DMsz, cudaMemcpyDeviceToDevice);

    for (int i = 0; i < NLsz; i++) {
        const float* rms = rms_w + (size_t)i * DMsz;
        const float* inw = in_w  + (size_t)i * 2 * EDsz * DMsz;
        const float* w1c = c1_w + (size_t)i * EDsz * 2;
        const float* b1c = c1_b + (size_t)i * EDsz;
        const float* w2c = c2_w + (size_t)i * EDsz * 2;
        const float* b2c = c2_b + (size_t)i * EDsz;
        const float* xpw = xp_w + (size_t)i * DCsz * EDsz;
        const float* dtw = dt_w + (size_t)i * EDsz * DTRsz;
        const float* dtb = dt_b + (size_t)i * EDsz;
        const float* alg = A_log + (size_t)i * EDsz * 2;
        const float* dpp = Dp + (size_t)i * EDsz;
        const float* ow  = out_w + (size_t)i * DMsz * EDsz;
        const float* k1w = k1_w + (size_t)i * 3 * EDsz * EDsz;
        const float* k1b = k1_b + (size_t)i * 3 * EDsz;
        const float* k2w = k2_w + (size_t)i * EDsz * 3 * EDsz;
        const float* k3w = k3_w + (size_t)i * EDsz * EDsz;
        const float* lng = ln_g + (size_t)i * EDsz;
        const float* lnb = ln_b + (size_t)i * EDsz;
        const float* kal = k_al + (size_t)i * EDsz;
        const float* sig = sigma + i;

        // weight converts (once per layer)
        wconv_k<<<(2*EDsz*DMsz)/256, 256>>>(inw, inwh, 2*EDsz*DMsz);
        wconv_k<<<(3*EDsz*EDsz)/256, 256>>>(k1w, k1wh, 3*EDsz*EDsz);
        wconv_k<<<(3*EDsz*EDsz)/256, 256>>>(k2w, k2wh, 3*EDsz*EDsz);
        wconv_k<<<(EDsz*EDsz)/256, 256>>>(k3w, k3wh, EDsz*EDsz);
        wconv_k<<<(DMsz*EDsz)/256, 256>>>(ow, owh, DMsz*EDsz);
        xppad_k<<<(128*EDsz)/256, 256>>>(xpw, xpwh);

        rmsnorm_k<<<MROWS, 256>>>(h, rms, xnh);

        // xz = xn @ in_w^T   (8192 x 4096, K=1024)
        ts_gemm_k<0,false><<<dim3(32, 64), 256>>>(
            xnh, inwh, xz, nullptr, DMsz, DMsz, 2*EDsz, 2*EDsz, DMsz, nullptr);

        conv_silu_k<<<(MROWS * EDsz) / 256, 256>>>(xz, w1c, b1c, w2c, b2c, xs, xsh);

        // dC = xs @ xp_w^T   (8192 x 66, K=2048) via padded xp_w
        ts_gemm_k<0,false><<<dim3(1, 64), 256>>>(
            xsh, xpwh, dC, nullptr, EDsz, EDsz, DCsz, DCsz, EDsz, nullptr);

        // delta = softplus(dr @ dt_w^T + dt_b)   (8192 x 2048, K=64)  [fp32 SIMT]
        gemm_sp_k<<<dim3(16, 64), 256>>>(dC, DCsz, dtw, DTRsz,
                                         delta, EDsz, EDsz, DTRsz, dtb);

        zero_k<<<(SROWS * EDsz) / 256, 256>>>(K, SROWS * EDsz);

        for (int s = 0; s < NSEG; s++) {
            int s0 = s * SEGsz;

            kerr_k<<<(SROWS * EDsz) / 256, 256>>>(xs, y, keh, s0, s == 0 ? 1 : 0);

            // kproj1: h1 = relu(Kerr @ k1_w^T + b)  (1024 x 6144, K=2048) -> fp16
            ts_gemm_k<1,true><<<dim3(48, 8), 256>>>(
                keh, k1wh, nullptr, h1h, EDsz, EDsz, 3*EDsz, 3*EDsz, EDsz, k1b);
            // kproj2: h2 = relu(h1 @ k2_w^T)        (1024 x 2048, K=6144) -> fp16
            ts_gemm_k<2,true><<<dim3(16, 8), 256>>>(
                h1h, k2wh, nullptr, h2h, 3*EDsz, 3*EDsz, EDsz, EDsz, 3*EDsz, nullptr);
            // kproj3: h3 = h2 @ k3_w^T              (1024 x 2048, K=2048) -> fp32
            ts_gemm_k<0,false><<<dim3(16, 8), 256>>>(
                h2h, k3wh, h3, nullptr, EDsz, EDsz, EDsz, EDsz, EDsz, nullptr);

            kup_k<<<SROWS, 256>>>(h3, lng, lnb, kal, K);

            // FDU stage 1: [Xr; Xi] = dft1 @ xg   (512 x 2048, K=256, batch=B)
            tgemm_nn_k<<<dim3(16, 4, Bsz), 256>>>(dft1, SEGsz, 0,
                                                  xs + (size_t)s0 * EDsz, EDsz, SBX,
                                                  Xf, EDsz, SBZ, SEGsz);
            czi_k<<<(SROWS * EDsz) / 256, 256>>>(Xf, delta, Zb, sig, s0);
            // FDU stage 2: Y = dft2 @ [Zr; Zi]    (256 x 2048, K=512, batch=B)
            tgemm_nn_k<<<dim3(16, 2, Bsz), 256>>>(dft2, 2 * SEGsz, 0,
                                                  Zb, EDsz, SBZ,
                                                  Yf, EDsz, SCY, 2 * SEGsz);

            scan_k<<<Bsz * (EDsz / 128), 128>>>(K, delta, xs, Yf, dC, alg, dpp, y, s0);
        }

        gate_k<<<(MROWS * EDsz) / 256, 256>>>(y, xz, ygh);

        // h += yg @ out_w^T   (8192 x 1024, K=2048)  [accumulate]
        ts_gemm_k<4,false><<<dim3(8, 64), 256>>>(
            ygh, owh, h, nullptr, EDsz, EDsz, DMsz, DMsz, EDsz, nullptr);
    }
}

// round 11
// speedup vs baseline: 5.6668x; 1.7175x over previous
#include <cuda_runtime.h>
#include <cuda_fp16.h>
#include <math.h>
#include <stdint.h>

// ---------------- problem constants ----------------
#define Bsz   4
#define Lsz   2048
#define DMsz  1024
#define EDsz  2048
#define SEGsz 256
#define NSEG  8
#define NLsz  2
#define DTRsz 64
#define DCsz  66   // DTR + N

// ---------------- fp32 scratch ----------------
__device__ float g_xz   [(size_t)Bsz*Lsz*2*EDsz];
__device__ float g_xs   [(size_t)Bsz*Lsz*EDsz];
__device__ float g_delta[(size_t)Bsz*Lsz*EDsz];
__device__ float g_dC   [(size_t)Bsz*Lsz*DCsz];
__device__ float g_y    [(size_t)Bsz*Lsz*EDsz];
__device__ float g_K    [(size_t)Bsz*SEGsz*EDsz];
__device__ float g_h3   [(size_t)Bsz*SEGsz*EDsz];
__device__ float g_Xf   [(size_t)Bsz*NSEG*2*SEGsz*EDsz];
__device__ float g_Zb   [(size_t)Bsz*NSEG*2*SEGsz*EDsz];
__device__ float g_Yf   [(size_t)Bsz*Lsz*EDsz];
__device__ float g_dft1 [2*SEGsz*SEGsz];
__device__ float g_dft2 [SEGsz*2*SEGsz];

// ---------------- fp16 operands ----------------
__device__ __half g_xnh [(size_t)Bsz*Lsz*DMsz];
__device__ __half g_inwh[(size_t)2*EDsz*DMsz];
__device__ __half g_xsh [(size_t)Bsz*Lsz*EDsz];
__device__ __half g_xpwh[(size_t)128*EDsz];
__device__ __half g_keh [(size_t)Bsz*SEGsz*EDsz];
__device__ __half g_k1wh[(size_t)3*EDsz*EDsz];
__device__ __half g_h1h [(size_t)Bsz*SEGsz*3*EDsz];
__device__ __half g_k2wh[(size_t)EDsz*3*EDsz];
__device__ __half g_h2h [(size_t)Bsz*SEGsz*EDsz];
__device__ __half g_k3wh[(size_t)EDsz*EDsz];
__device__ __half g_ygh [(size_t)Bsz*Lsz*EDsz];
__device__ __half g_owh [(size_t)DMsz*EDsz];

// ---------------- small helpers ----------------
__device__ __forceinline__ uint2 pack4h(float a, float b, float c, float d) {
    __half2 h0 = __floats2half2_rn(a, b), h1 = __floats2half2_rn(c, d);
    uint2 u; u.x = *(uint32_t*)&h0; u.y = *(uint32_t*)&h1; return u;
}
__device__ __forceinline__ uint4 pack8h(float4 a, float4 b) {
    __half2 h0 = __floats2half2_rn(a.x, a.y), h1 = __floats2half2_rn(a.z, a.w);
    __half2 h2 = __floats2half2_rn(b.x, b.y), h3 = __floats2half2_rn(b.z, b.w);
    uint4 u; u.x = *(uint32_t*)&h0; u.y = *(uint32_t*)&h1;
    u.z = *(uint32_t*)&h2; u.w = *(uint32_t*)&h3; return u;
}
__device__ __forceinline__ float blkSum(float v) {
    __shared__ float sh[32];
    __syncthreads();
    int lane = threadIdx.x & 31, w = threadIdx.x >> 5;
#pragma unroll
    for (int o = 16; o; o >>= 1) v += __shfl_down_sync(0xffffffffu, v, o);
    if (!lane) sh[w] = v;
    __syncthreads();
    if (w == 0) {
        v = (lane < (int)(blockDim.x >> 5)) ? sh[lane] : 0.f;
#pragma unroll
        for (int o = 16; o; o >>= 1) v += __shfl_down_sync(0xffffffffu, v, o);
        if (!lane) sh[0] = v;
    }
    __syncthreads();
    return sh[0];
}

// ---------------- mma / async primitives ----------------
__device__ __forceinline__ void mma16816(float* d, const uint32_t* a, uint32_t b0, uint32_t b1) {
    asm volatile(
        "mma.sync.aligned.m16n8k16.row.col.f32.f16.f16.f32 "
        "{%0,%1,%2,%3}, {%4,%5,%6,%7}, {%8,%9}, {%0,%1,%2,%3};\n"
        : "+f"(d[0]), "+f"(d[1]), "+f"(d[2]), "+f"(d[3])
        : "r"(a[0]), "r"(a[1]), "r"(a[2]), "r"(a[3]), "r"(b0), "r"(b1));
}
__device__ __forceinline__ void ldsm4(uint32_t* r, uint32_t addr) {
    asm volatile("ldmatrix.sync.aligned.m8n8.x4.shared.b16 {%0,%1,%2,%3}, [%4];\n"
        : "=r"(r[0]), "=r"(r[1]), "=r"(r[2]), "=r"(r[3]) : "r"(addr));
}
__device__ __forceinline__ void cpa16(uint32_t dst, const void* src) {
    asm volatile("cp.async.cg.shared.global [%0], [%1], 16;\n" :: "r"(dst), "l"(src));
}
__device__ __forceinline__ void cpa_commit() { asm volatile("cp.async.commit_group;\n" ::: "memory"); }
template<int N> __device__ __forceinline__ void cpa_wait() {
    asm volatile("cp.async.wait_group %0;\n" :: "n"(N) : "memory");
}

// ================= single-fp16 mma.sync GEMM =================
// D = A(MxK) @ B(NxK)^T, fp16 inputs, fp32 accum.
// EPI: 0 none, 1 bias+relu, 2 relu, 4 C += result.  PAIR: emit fp16 output.
#define TS_STAGE 16384
template<int EPI, bool PAIR>
__global__ __launch_bounds__(256) void ts_gemm_k(
    const __half* __restrict__ Ahg, const __half* __restrict__ Bhg,
    float* __restrict__ C, __half* __restrict__ Oh,
    int lda, int ldb, int ldc, int Nn, int K, const float* __restrict__ bias)
{
    __shared__ __align__(16) char sm[2 * TS_STAGE];
    const int tid = threadIdx.x;
    const int lane = tid & 31, wid = tid >> 5;
    const int wm = wid & 1, wn = wid >> 1;
    const int m0 = blockIdx.y * 128, n0 = blockIdx.x * 128;

    float acc[4][4][4];
#pragma unroll
    for (int i = 0; i < 4; i++)
#pragma unroll
        for (int j = 0; j < 4; j++)
#pragma unroll
            for (int q = 0; q < 4; q++) acc[i][j][q] = 0.f;

    const uint32_t smBase = (uint32_t)__cvta_generic_to_shared(sm);
    const int frow0 = tid >> 2;
    const int fc    = tid & 3;
    auto fill = [&](int k0, int st) {
        const uint32_t base = smBase + st * TS_STAGE;
#pragma unroll
        for (int i = 0; i < 2; i++) {
            int row = frow0 + i * 64;
            uint32_t off = (uint32_t)(row * 64 + fc * 16);
            uint32_t dsw = off ^ ((off >> 3) & 0x30);
            cpa16(base +        dsw, Ahg + (size_t)(m0 + row) * lda + k0 + fc * 8);
            cpa16(base + 8192 + dsw, Bhg + (size_t)(n0 + row) * ldb + k0 + fc * 8);
        }
        cpa_commit();
    };

    const int aRow = wm * 64 + (lane & 15);
    const int aCh  = (lane >> 4);
    const int bRow = wn * 32 + (lane & 7) + ((lane & 16) >> 1);
    const int bCh  = ((lane & 8) >> 3);

    const int kt = K >> 5;
    fill(0, 0);
    for (int t = 0; t < kt; t++) {
        if (t + 1 < kt) { fill((t + 1) << 5, (t + 1) & 1); cpa_wait<1>(); }
        else            { cpa_wait<0>(); }
        __syncthreads();
        const uint32_t base = smBase + (t & 1) * TS_STAGE;
#pragma unroll
        for (int ks = 0; ks < 2; ks++) {
            uint32_t bh[2][4];
#pragma unroll
            for (int nt2 = 0; nt2 < 2; nt2++) {
                uint32_t off = (uint32_t)((bRow + nt2 * 16) * 64 + (bCh + ks * 2) * 16);
                uint32_t dsw = off ^ ((off >> 3) & 0x30);
                ldsm4(bh[nt2], base + 8192 + dsw);
            }
#pragma unroll
            for (int mt = 0; mt < 4; mt++) {
                uint32_t off = (uint32_t)((aRow + mt * 16) * 64 + (aCh + ks * 2) * 16);
                uint32_t dsw = off ^ ((off >> 3) & 0x30);
                uint32_t ah[4];
                ldsm4(ah, base + dsw);
#pragma unroll
                for (int n8 = 0; n8 < 4; n8++)
                    mma16816(acc[mt][n8], ah, bh[n8 >> 1][(n8 & 1) * 2], bh[n8 >> 1][(n8 & 1) * 2 + 1]);
            }
        }
        __syncthreads();
    }

    const int g = lane >> 2, cc = (lane & 3) * 2;
#pragma unroll
    for (int mt = 0; mt < 4; mt++) {
        long long m = m0 + wm * 64 + mt * 16 + g;
#pragma unroll
        for (int n8 = 0; n8 < 4; n8++) {
            int col = n0 + wn * 32 + n8 * 8 + cc;
            if (col >= Nn) continue;
            float* a4 = acc[mt][n8];
            float2 v0 = make_float2(a4[0], a4[1]);
            float2 v1 = make_float2(a4[2], a4[3]);
            if (EPI == 1) {
                float b0 = bias[col], b1 = bias[col + 1];
                v0.x = fmaxf(v0.x + b0, 0.f); v0.y = fmaxf(v0.y + b1, 0.f);
                v1.x = fmaxf(v1.x + b0, 0.f); v1.y = fmaxf(v1.y + b1, 0.f);
            } else if (EPI == 2) {
                v0.x = fmaxf(v0.x, 0.f); v0.y = fmaxf(v0.y, 0.f);
                v1.x = fmaxf(v1.x, 0.f); v1.y = fmaxf(v1.y, 0.f);
            }
            if (PAIR) {
                *(__half2*)(Oh + m * ldc + col)       = __floats2half2_rn(v0.x, v0.y);
                *(__half2*)(Oh + (m + 8) * ldc + col) = __floats2half2_rn(v1.x, v1.y);
            } else {
                float* p0 = C + m * ldc + col;
                float* p1 = C + (m + 8) * ldc + col;
                if (EPI == 4) {
                    float2 o0 = *(float2*)p0, o1 = *(float2*)p1;
                    v0.x += o0.x; v0.y += o0.y; v1.x += o1.x; v1.y += o1.y;
                }
                *(float2*)p0 = v0;
                *(float2*)p1 = v1;
            }
        }
    }
}

// ---------------- DFT table init ----------------
__global__ void dft_init_k() {
    int idx = blockIdx.x * 256 + threadIdx.x;
    int t = idx & 255, k = idx >> 8;
    int p = (k * t) & 255;
    float ang = 6.283185307179586f * (float)p * (1.0f / 256.0f);
    float s, c;
    sincosf(ang, &s, &c);
    g_dft1[k * 256 + t]         = c;
    g_dft1[(k + 256) * 256 + t] = -s;
    g_dft2[t * 512 + k]         = c  * (1.0f / 256.0f);
    g_dft2[t * 512 + 256 + k]   = -s * (1.0f / 256.0f);
}

// ---------------- weight convert (fp32 -> fp16), 8 elems/thread ----------------
__global__ void wconv_k(const float* __restrict__ src, __half* __restrict__ dh, int n8) {
    int i = blockIdx.x * 256 + threadIdx.x;
    if (i >= n8) return;
    const float4* s = (const float4*)src + (size_t)i * 2;
    float4 a = s[0], b = s[1];
    *((uint4*)dh + i) = pack8h(a, b);
}
// xp_w padded to 128 rows (rows 66..127 zero), 8 elems/thread
__global__ void xppad_k(const float* __restrict__ src, __half* __restrict__ dh) {
    int i = blockIdx.x * 256 + threadIdx.x;   // 32768 threads
    int g0 = i * 8;
    int row = g0 >> 11, col = g0 & (EDsz - 1);
    float4 a = make_float4(0, 0, 0, 0), b = a;
    if (row < DCsz) {
        a = *(const float4*)(src + (size_t)row * EDsz + col);
        b = *(const float4*)(src + (size_t)row * EDsz + col + 4);
    }
    *((uint4*)dh + i) = pack8h(a, b);
}

// ---------------- RMSNorm -> fp16 (vectorized) ----------------
__global__ void rmsnorm_k(const float* __restrict__ h, const float* __restrict__ w,
                          __half* __restrict__ oh) {
    size_t base = (size_t)blockIdx.x * DMsz;
    int tid = threadIdx.x;                        // 256 threads x 4 = 1024
    float4 v = *((const float4*)(h + base) + tid);
    float s = v.x * v.x + v.y * v.y + v.z * v.z + v.w * v.w;
    s = blkSum(s);
    float r = rsqrtf(s * (1.0f / DMsz) + 1e-5f);
    float4 w4 = *((const float4*)w + tid);
    *((uint2*)(oh + base) + tid) = pack4h(v.x * r * w4.x, v.y * r * w4.y,
                                          v.z * r * w4.z, v.w * r * w4.w);
}

// ---------------- fused double depthwise conv (k=2) + SiLU (x4) ----------------
__global__ void conv_silu_k(const float* __restrict__ xz,
                            const float* __restrict__ c1w, const float* __restrict__ c1b,
                            const float* __restrict__ c2w, const float* __restrict__ c2b,
                            float* __restrict__ xs, __half* __restrict__ xsh) {
    size_t idx = (size_t)blockIdx.x * 256 + threadIdx.x;    // over B*L*ED/4
    size_t g0 = idx * 4;
    int e = (int)(g0 & (EDsz - 1));
    int l = (int)((g0 >> 11) & (Lsz - 1));
    int b = (int)(g0 >> 22);
    const float* base = xz + (size_t)(b * Lsz) * (2 * EDsz) + e;
    float4 x2 = *(const float4*)(base + (size_t)l * (2 * EDsz));
    float4 x1 = (l >= 1) ? *(const float4*)(base + (size_t)(l - 1) * (2 * EDsz)) : make_float4(0,0,0,0);
    float4 x0 = (l >= 2) ? *(const float4*)(base + (size_t)(l - 2) * (2 * EDsz)) : make_float4(0,0,0,0);
    float4 w1a = *(const float4*)(c1w + e * 2);
    float4 w1b = *(const float4*)(c1w + e * 2 + 4);
    float4 w2a = *(const float4*)(c2w + e * 2);
    float4 w2b = *(const float4*)(c2w + e * 2 + 4);
    float4 b1 = *(const float4*)(c1b + e);
    float4 b2 = *(const float4*)(c2b + e);
    float r[4];
    {
        float X0[4] = {x0.x, x0.y, x0.z, x0.w};
        float X1[4] = {x1.x, x1.y, x1.z, x1.w};
        float X2[4] = {x2.x, x2.y, x2.z, x2.w};
        float W10[4] = {w1a.x, w1a.z, w1b.x, w1b.z};
        float W11[4] = {w1a.y, w1a.w, w1b.y, w1b.w};
        float W20[4] = {w2a.x, w2a.z, w2b.x, w2b.z};
        float W21[4] = {w2a.y, w2a.w, w2b.y, w2b.w};
        float B1[4] = {b1.x, b1.y, b1.z, b1.w};
        float B2[4] = {b2.x, b2.y, b2.z, b2.w};
#pragma unroll
        for (int j = 0; j < 4; j++) {
            float y1a = (l >= 1) ? (B1[j] + X0[j] * W10[j] + X1[j] * W11[j]) : 0.f;
            float y1b = B1[j] + X1[j] * W10[j] + X2[j] * W11[j];
            float y2 = B2[j] + y1a * W20[j] + y1b * W21[j];
            r[j] = y2 / (1.f + __expf(-y2));
        }
    }
    *(float4*)(xs + g0) = make_float4(r[0], r[1], r[2], r[3]);
    *(uint2*)(xsh + g0) = pack4h(r[0], r[1], r[2], r[3]);
}

// ---------------- fp16 NN GEMM (FDU, batched): C = A(MxK) @ B(KxN) -------------
__global__ __launch_bounds__(256) void tgemm_nn_k(
    const float* __restrict__ A, int lda, long long sA,
    const float* __restrict__ Bm, int ldb, long long sB,
    float* __restrict__ C, int ldc, long long sC,
    int K)
{
    __shared__ __align__(16) __half Ah[128][40];
    __shared__ __align__(16) __half Bh[128][40];

    const int bz = blockIdx.z;
    A  += (long long)bz * sA;
    Bm += (long long)bz * sB;
    C  += (long long)bz * sC;
    const int m0 = blockIdx.y * 128, n0 = blockIdx.x * 128;
    const int tid = threadIdx.x;
    const int lane = tid & 31, wid = tid >> 5;
    const int wm = wid & 1, wn = wid >> 1;

    float acc[4][4][4];
#pragma unroll
    for (int i = 0; i < 4; i++)
#pragma unroll
        for (int j = 0; j < 4; j++)
#pragma unroll
            for (int q = 0; q < 4; q++) acc[i][j][q] = 0.f;

    const int ak4 = tid & 7;
    const int ar0 = tid >> 3;
    const int bn4 = tid & 31;
    const int bk0 = tid >> 5;

    float4 av[4], bv[4];
    auto loadTile = [&](int k0) {
        const float* pa = A + (long long)(m0 + ar0) * lda + k0 + ak4 * 4;
#pragma unroll
        for (int i = 0; i < 4; i++) av[i] = *(const float4*)(pa + (long long)(32 * i) * lda);
        const float* pb = Bm + (long long)(k0 + bk0) * ldb + n0 + bn4 * 4;
#pragma unroll
        for (int i = 0; i < 4; i++) bv[i] = *(const float4*)(pb + (long long)(8 * i) * ldb);
    };
    auto storeTile = [&]() {
#pragma unroll
        for (int i = 0; i < 4; i++) {
            int row = ar0 + 32 * i;
            float4 v = av[i];
            __half2* dh = (__half2*)&Ah[row][ak4 * 4];
            dh[0] = __floats2half2_rn(v.x, v.y);
            dh[1] = __floats2half2_rn(v.z, v.w);
        }
#pragma unroll
        for (int i = 0; i < 4; i++) {
            int kr = bk0 + 8 * i;
            float4 v = bv[i];
            float s4[4] = {v.x, v.y, v.z, v.w};
#pragma unroll
            for (int j = 0; j < 4; j++)
                Bh[bn4 * 4 + j][kr] = __float2half_rn(s4[j]);
        }
    };

    const uint32_t aBase = (uint32_t)__cvta_generic_to_shared(&Ah[0][0]);
    const uint32_t bBase = (uint32_t)__cvta_generic_to_shared(&Bh[0][0]);
    const uint32_t aOff = ((wm * 64 + (lane & 15)) * 40 + ((lane >> 4) << 3)) * 2;
    const uint32_t bOff = ((wn * 32 + (lane & 7) + ((lane & 16) >> 1)) * 40 + (lane & 8)) * 2;

    const int kt = K >> 5;
    loadTile(0);
    for (int t = 0; t < kt; t++) {
        storeTile();
        __syncthreads();
        if (t + 1 < kt) loadTile((t + 1) << 5);
#pragma unroll
        for (int ks = 0; ks < 2; ks++) {
            uint32_t bhf[2][4];
#pragma unroll
            for (int nt2 = 0; nt2 < 2; nt2++)
                ldsm4(bhf[nt2], bBase + bOff + nt2 * 16 * 80 + ks * 32);
#pragma unroll
            for (int mt = 0; mt < 4; mt++) {
                uint32_t ahf[4];
                ldsm4(ahf, aBase + aOff + mt * 16 * 80 + ks * 32);
#pragma unroll
                for (int n8 = 0; n8 < 4; n8++)
                    mma16816(acc[mt][n8], ahf, bhf[n8 >> 1][(n8 & 1) * 2], bhf[n8 >> 1][(n8 & 1) * 2 + 1]);
            }
        }
        __syncthreads();
    }

    const int g = lane >> 2, cc = (lane & 3) * 2;
#pragma unroll
    for (int mt = 0; mt < 4; mt++) {
        long long m = m0 + wm * 64 + mt * 16 + g;
#pragma unroll
        for (int n8 = 0; n8 < 4; n8++) {
            int col = n0 + wn * 32 + n8 * 8 + cc;
            float* a4 = acc[mt][n8];
            *(float2*)(C + m * ldc + col)       = make_float2(a4[0], a4[1]);
            *(float2*)(C + (m + 8) * ldc + col) = make_float2(a4[2], a4[3]);
        }
    }
}

// ---------------- SIMT fp32 GEMM (delta only: bias+softplus) ----------------
__global__ __launch_bounds__(256) void gemm_sp_k(
    const float* __restrict__ A, int lda,
    const float* __restrict__ Bm, int ldb,
    float* __restrict__ C, int ldc,
    int N, int K, const float* __restrict__ bias)
{
    __shared__ float As[16][128];
    __shared__ float Bs[16][132];
    const int m0 = blockIdx.y * 128, n0 = blockIdx.x * 128;
    const int tid = threadIdx.x;
    const int tx = tid & 15, ty = tid >> 4;
    float acc[8][8];
#pragma unroll
    for (int i = 0; i < 8; i++)
#pragma unroll
        for (int j = 0; j < 8; j++) acc[i][j] = 0.f;
    const bool a4 = ((lda & 3) == 0);

    for (int k0 = 0; k0 < K; k0 += 16) {
        {
            int r = tid >> 2, c4 = (tid & 3) << 2;
#pragma unroll
            for (int rr = 0; rr < 2; rr++) {
                int row = r + rr * 64;
                const float* p = A + (long long)(m0 + row) * lda + (k0 + c4);
                float4 v;
                if (a4) v = *(const float4*)p;
                else { v.x = p[0]; v.y = p[1]; v.z = p[2]; v.w = p[3]; }
                As[c4 + 0][row] = v.x; As[c4 + 1][row] = v.y;
                As[c4 + 2][row] = v.z; As[c4 + 3][row] = v.w;
            }
        }
        {
            int r = tid >> 2, c4 = (tid & 3) << 2;
#pragma unroll
            for (int rr = 0; rr < 2; rr++) {
                int row = r + rr * 64;
                float4 v = make_float4(0.f, 0.f, 0.f, 0.f);
                if (n0 + row < N) {
                    const float* p = Bm + (long long)(n0 + row) * ldb + (k0 + c4);
                    v.x = p[0]; v.y = p[1]; v.z = p[2]; v.w = p[3];
                }
                Bs[c4 + 0][row] = v.x; Bs[c4 + 1][row] = v.y;
                Bs[c4 + 2][row] = v.z; Bs[c4 + 3][row] = v.w;
            }
        }
        __syncthreads();
#pragma unroll
        for (int kk = 0; kk < 16; kk++) {
            float a[8], b[8];
            *(float4*)&a[0] = *(const float4*)&As[kk][ty * 8];
            *(float4*)&a[4] = *(const float4*)&As[kk][ty * 8 + 4];
            *(float4*)&b[0] = *(const float4*)&Bs[kk][tx * 8];
            *(float4*)&b[4] = *(const float4*)&Bs[kk][tx * 8 + 4];
#pragma unroll
            for (int i = 0; i < 8; i++)
#pragma unroll
                for (int j = 0; j < 8; j++)
                    acc[i][j] = fmaf(a[i], b[j], acc[i][j]);
        }
        __syncthreads();
    }
#pragma unroll
    for (int ii = 0; ii < 8; ii++) {
        long long m = m0 + ty * 8 + ii;
        float* Crow = C + m * (long long)ldc;
#pragma unroll
        for (int jj = 0; jj < 8; jj++) {
            int n = n0 + tx * 8 + jj;
            if (n >= N) continue;
            float v = acc[ii][jj] + bias[n];
            Crow[n] = (v > 20.f) ? v : log1pf(expf(v));
        }
    }
}

// ---------------- zero fill (x4) ----------------
__global__ void zero_k(float* p, int n4) {
    int i = blockIdx.x * 256 + threadIdx.x;
    if (i < n4) ((float4*)p)[i] = make_float4(0, 0, 0, 0);
}

// ---------------- Kerr = softsign((xg - yh)^2) -> fp16 (x4) ----------------
__global__ void kerr_k(const float* __restrict__ xs, const float* __restrict__ y,
                       __half* __restrict__ kh, int s0, int first) {
    size_t idx = (size_t)blockIdx.x * 256 + threadIdx.x;   // B*SEG*ED/4
    size_t g0 = idx * 4;
    int e = (int)(g0 & (EDsz - 1));
    int t = (int)((g0 >> 11) & (SEGsz - 1));
    int b = (int)(g0 >> 19);
    float4 xg = *(const float4*)(xs + ((size_t)(b * Lsz + s0 + t)) * EDsz + e);
    float4 yh = make_float4(0, 0, 0, 0);
    if (!first) yh = *(const float4*)(y + ((size_t)(b * Lsz + s0 - SEGsz + t)) * EDsz + e);
    float r[4];
    float dx[4] = {xg.x - yh.x, xg.y - yh.y, xg.z - yh.z, xg.w - yh.w};
#pragma unroll
    for (int j = 0; j < 4; j++) { float d = dx[j] * dx[j]; r[j] = d / (1.f + d); }
    *(uint2*)(kh + g0) = pack4h(r[0], r[1], r[2], r[3]);
}

// ---------------- LayerNorm(h3) -> Knew; K = (1-a)K + a*Knew (x8) ----------------
__global__ void kup_k(const float* __restrict__ h3,
                      const float* __restrict__ lng, const float* __restrict__ lnb,
                      const float* __restrict__ kal, float* __restrict__ K) {
    size_t base = (size_t)blockIdx.x * EDsz;
    int e0 = threadIdx.x * 8;
    float4 va = *(const float4*)(h3 + base + e0);
    float4 vb = *(const float4*)(h3 + base + e0 + 4);
    float v[8] = {va.x, va.y, va.z, va.w, vb.x, vb.y, vb.z, vb.w};
    float s = 0.f;
#pragma unroll
    for (int j = 0; j < 8; j++) s += v[j];
    s = blkSum(s);
    float mu = s * (1.0f / EDsz);
    float q = 0.f;
#pragma unroll
    for (int j = 0; j < 8; j++) { float d = v[j] - mu; q += d * d; }
    q = blkSum(q);
    float rstd = rsqrtf(q * (1.0f / EDsz) + 1e-5f);
    float4 ga = *(const float4*)(lng + e0), gb = *(const float4*)(lng + e0 + 4);
    float4 ba = *(const float4*)(lnb + e0), bb = *(const float4*)(lnb + e0 + 4);
    float4 aa = *(const float4*)(kal + e0), ab = *(const float4*)(kal + e0 + 4);
    float4 ka = *(const float4*)(K + base + e0), kb = *(const float4*)(K + base + e0 + 4);
    float gv[8] = {ga.x, ga.y, ga.z, ga.w, gb.x, gb.y, gb.z, gb.w};
    float bv[8] = {ba.x, ba.y, ba.z, ba.w, bb.x, bb.y, bb.z, bb.w};
    float av2[8] = {aa.x, aa.y, aa.z, aa.w, ab.x, ab.y, ab.z, ab.w};
    float kv[8] = {ka.x, ka.y, ka.z, ka.w, kb.x, kb.y, kb.z, kb.w};
#pragma unroll
    for (int j = 0; j < 8; j++) {
        float kn = gv[j] * (v[j] - mu) * rstd + bv[j];
        float a = fminf(fmaxf(av2[j], 0.01f), 0.99f);
        kv[j] = (1.f - a) * kv[j] + a * kn;
    }
    *(float4*)(K + base + e0)     = make_float4(kv[0], kv[1], kv[2], kv[3]);
    *(float4*)(K + base + e0 + 4) = make_float4(kv[4], kv[5], kv[6], kv[7]);
}

// ---------------- FDU middle: Z = i*c scaling (batched over B*NSEG, x4) ---------
__global__ void czi_k(const float* __restrict__ Xf, const float* __restrict__ delta,
                      float* __restrict__ Z, const float* __restrict__ sigp) {
    size_t idx = (size_t)blockIdx.x * 256 + threadIdx.x;   // B*NSEG*SEG*ED/4
    size_t g0 = idx * 4;
    int e = (int)(g0 & (EDsz - 1));
    int k = (int)((g0 >> 11) & (SEGsz - 1));
    int z = (int)(g0 >> 19);
    float sig = sigp[0];
    float f = (float)((k < 128) ? k : k - 256) * (1.0f / 256.0f);
    float gk = __expf(-f * f * sig * sig);
    float w = 6.283185307179586f * f * gk;
    float4 dt = *(const float4*)(delta + ((size_t)z * SEGsz + k) * EDsz + e);
    size_t base = ((size_t)z * 2 * SEGsz + k) * EDsz + e;
    float4 xr = *(const float4*)(Xf + base);
    float4 xi = *(const float4*)(Xf + base + (size_t)SEGsz * EDsz);
    float c0 = w / (dt.x + 1e-5f), c1 = w / (dt.y + 1e-5f);
    float c2 = w / (dt.z + 1e-5f), c3 = w / (dt.w + 1e-5f);
    *(float4*)(Z + base) = make_float4(-c0 * xi.x, -c1 * xi.y, -c2 * xi.z, -c3 * xi.w);
    *(float4*)(Z + base + (size_t)SEGsz * EDsz) = make_float4(c0 * xr.x, c1 * xr.y, c2 * xr.z, c3 * xr.w);
}

// ---------------- segment scan (software prefetch) ----------------
__global__ void scan_k(const float* __restrict__ K, const float* __restrict__ delta,
                       const float* __restrict__ xs, const float* __restrict__ Yf,
                       const float* __restrict__ dC, const float* __restrict__ Alog,
                       const float* __restrict__ Dpv, float* __restrict__ y, int s0) {
    int b = blockIdx.x >> 4;
    int e = ((blockIdx.x & 15) << 7) + threadIdx.x;
    float A0 = -__expf(Alog[e * 2 + 0]);
    float A1 = -__expf(Alog[e * 2 + 1]);
    float Dpe = Dpv[e];
    float h0 = 0.f, h1 = 0.f;
    size_t rL = (size_t)(b * Lsz + s0);
    size_t rS = (size_t)(b * SEGsz);
    float Kv = K[rS * EDsz + e];
    float dg = delta[rL * EDsz + e];
    float xv = xs[rL * EDsz + e];
    float Yv = Yf[rL * EDsz + e];
    float C0 = __ldg(dC + rL * DCsz + 64);
    float C1 = __ldg(dC + rL * DCsz + 65);
    for (int t = 0; t < SEGsz; t++) {
        float Kn = 0.f, dn = 0.f, xn = 0.f, Yn = 0.f, C0n = 0.f, C1n = 0.f;
        if (t + 1 < SEGsz) {
            Kn  = K[(rS + 1) * EDsz + e];
            dn  = delta[(rL + 1) * EDsz + e];
            xn  = xs[(rL + 1) * EDsz + e];
            Yn  = Yf[(rL + 1) * EDsz + e];
            C0n = __ldg(dC + (rL + 1) * DCsz + 64);
            C1n = __ldg(dC + (rL + 1) * DCsz + 65);
        }
        float Kdy = Kv * Yv;
        {
            float KC = Kv * C0;
            float AmK = A0 * (1.f - KC);
            float Ak  = AmK * (1.f + KC);
            float Bk  = -AmK * Kv;
            float dA  = __expf(dg * Ak);
            h0 = dA * h0 + dg * Bk * xv + Kdy;
        }
        {
            float KC = Kv * C1;
            float AmK = A1 * (1.f - KC);
            float Ak  = AmK * (1.f + KC);
            float Bk  = -AmK * Kv;
            float dA  = __expf(dg * Ak);
            h1 = dA * h1 + dg * Bk * xv + Kdy;
        }
        y[rL * EDsz + e] = h0 * C0 + h1 * C1 + Dpe * xv;
        rL++; rS++;
        Kv = Kn; dg = dn; xv = xn; Yv = Yn; C0 = C0n; C1 = C1n;
    }
}

// ---------------- gate: yg = y * silu(z) -> fp16 (x4) ----------------
__global__ void gate_k(const float* __restrict__ y, const float* __restrict__ xz,
                       __half* __restrict__ gh) {
    size_t idx = (size_t)blockIdx.x * 256 + threadIdx.x;   // B*L*ED/4
    size_t g0 = idx * 4;
    int e = (int)(g0 & (EDsz - 1));
    size_t row = g0 >> 11;
    float4 z = *(const float4*)(xz + row * (2 * EDsz) + EDsz + e);
    float4 yv = *(const float4*)(y + g0);
    float r0 = yv.x * z.x / (1.f + __expf(-z.x));
    float r1 = yv.y * z.y / (1.f + __expf(-z.y));
    float r2 = yv.z * z.z / (1.f + __expf(-z.z));
    float r3 = yv.w * z.w / (1.f + __expf(-z.w));
    *(uint2*)(gh + g0) = pack4h(r0, r1, r2, r3);
}

// ---------------- host ----------------
static float* symAddr(const void* sym) {
    void* p = nullptr;
    cudaGetSymbolAddress(&p, sym);
    return (float*)p;
}
static __half* symAddrH(const void* sym) {
    void* p = nullptr;
    cudaGetSymbolAddress(&p, sym);
    return (__half*)p;
}

extern "C" void kernel_launch(void* const* d_in, const int* in_sizes, int n_in,
                              void* d_out, int out_size) {
    const float* x     = (const float*)d_in[0];
    const float* rms_w = (const float*)d_in[1];
    const float* in_w  = (const float*)d_in[2];
    const float* c1_w  = (const float*)d_in[3];
    const float* c1_b  = (const float*)d_in[4];
    const float* c2_w  = (const float*)d_in[5];
    const float* c2_b  = (const float*)d_in[6];
    const float* xp_w  = (const float*)d_in[7];
    const float* dt_w  = (const float*)d_in[8];
    const float* dt_b  = (const float*)d_in[9];
    const float* A_log = (const float*)d_in[10];
    const float* Dp    = (const float*)d_in[11];
    const float* out_w = (const float*)d_in[12];
    const float* k1_w  = (const float*)d_in[13];
    const float* k1_b  = (const float*)d_in[14];
    const float* k2_w  = (const float*)d_in[15];
    const float* k3_w  = (const float*)d_in[16];
    const float* ln_g  = (const float*)d_in[17];
    const float* ln_b  = (const float*)d_in[18];
    const float* k_al  = (const float*)d_in[19];
    const float* sigma = (const float*)d_in[20];

    float* xz    = symAddr(g_xz);
    float* xs    = symAddr(g_xs);
    float* delta = symAddr(g_delta);
    float* dC    = symAddr(g_dC);
    float* y     = symAddr(g_y);
    float* K     = symAddr(g_K);
    float* h3    = symAddr(g_h3);
    float* Xf    = symAddr(g_Xf);
    float* Zb    = symAddr(g_Zb);
    float* Yf    = symAddr(g_Yf);
    float* dft1  = symAddr(g_dft1);
    float* dft2  = symAddr(g_dft2);
    __half *xnh = symAddrH(g_xnh);
    __half *inwh= symAddrH(g_inwh);
    __half *xsh = symAddrH(g_xsh);
    __half *xpwh= symAddrH(g_xpwh);
    __half *keh = symAddrH(g_keh);
    __half *k1wh= symAddrH(g_k1wh);
    __half *h1h = symAddrH(g_h1h);
    __half *k2wh= symAddrH(g_k2wh);
    __half *h2h = symAddrH(g_h2h);
    __half *k3wh= symAddrH(g_k3wh);
    __half *ygh = symAddrH(g_ygh);
    __half *owh = symAddrH(g_owh);
    float* h = (float*)d_out;

    const int MROWS = Bsz * Lsz;              // 8192
    const int SROWS = Bsz * SEGsz;            // 1024
    const int NB = Bsz * NSEG;                // 32 FDU batches

    dft_init_k<<<256, 256>>>();
    cudaMemcpyAsync(h, x, sizeof(float) * (size_t)MROWS * DMsz, cudaMemcpyDeviceToDevice);

    for (int i = 0; i < NLsz; i++) {
        const float* rms = rms_w + (size_t)i * DMsz;
        const float* inw = in_w  + (size_t)i * 2 * EDsz * DMsz;
        const float* w1c = c1_w + (size_t)i * EDsz * 2;
        const float* b1c = c1_b + (size_t)i * EDsz;
        const float* w2c = c2_w + (size_t)i * EDsz * 2;
        const float* b2c = c2_b + (size_t)i * EDsz;
        const float* xpw = xp_w + (size_t)i * DCsz * EDsz;
        const float* dtw = dt_w + (size_t)i * EDsz * DTRsz;
        const float* dtb = dt_b + (size_t)i * EDsz;
        const float* alg = A_log + (size_t)i * EDsz * 2;
        const float* dpp = Dp + (size_t)i * EDsz;
        const float* ow  = out_w + (size_t)i * DMsz * EDsz;
        const float* k1w = k1_w + (size_t)i * 3 * EDsz * EDsz;
        const float* k1b = k1_b + (size_t)i * 3 * EDsz;
        const float* k2w = k2_w + (size_t)i * EDsz * 3 * EDsz;
        const float* k3w = k3_w + (size_t)i * EDsz * EDsz;
        const float* lng = ln_g + (size_t)i * EDsz;
        const float* lnb = ln_b + (size_t)i * EDsz;
        const float* kal = k_al + (size_t)i * EDsz;
        const float* sig = sigma + i;

        // weight converts (vectorized x8)
        wconv_k<<<(2*EDsz*DMsz/8 + 255)/256, 256>>>(inw, inwh, 2*EDsz*DMsz/8);
        wconv_k<<<(3*EDsz*EDsz/8 + 255)/256, 256>>>(k1w, k1wh, 3*EDsz*EDsz/8);
        wconv_k<<<(3*EDsz*EDsz/8 + 255)/256, 256>>>(k2w, k2wh, 3*EDsz*EDsz/8);
        wconv_k<<<(EDsz*EDsz/8 + 255)/256, 256>>>(k3w, k3wh, EDsz*EDsz/8);
        wconv_k<<<(DMsz*EDsz/8 + 255)/256, 256>>>(ow, owh, DMsz*EDsz/8);
        xppad_k<<<(128*EDsz/8)/256, 256>>>(xpw, xpwh);

        rmsnorm_k<<<MROWS, 256>>>(h, rms, xnh);

        // xz = xn @ in_w^T   (8192 x 4096, K=1024)
        ts_gemm_k<0,false><<<dim3(32, 64), 256>>>(
            xnh, inwh, xz, nullptr, DMsz, DMsz, 2*EDsz, 2*EDsz, DMsz, nullptr);

        conv_silu_k<<<(MROWS * EDsz / 4) / 256, 256>>>(xz, w1c, b1c, w2c, b2c, xs, xsh);

        // dC = xs @ xp_w^T   (8192 x 66, K=2048) via padded xp_w
        ts_gemm_k<0,false><<<dim3(1, 64), 256>>>(
            xsh, xpwh, dC, nullptr, EDsz, EDsz, DCsz, DCsz, EDsz, nullptr);

        // delta = softplus(dr @ dt_w^T + dt_b)
        gemm_sp_k<<<dim3(16, 64), 256>>>(dC, DCsz, dtw, DTRsz,
                                         delta, EDsz, EDsz, DTRsz, dtb);

        // ----- batched FDU over all 8 segments (hoisted out of seg loop) -----
        // stage 1: [Xr; Xi] = dft1 @ xs_seg   (512 x 2048, K=256, batch=32)
        tgemm_nn_k<<<dim3(16, 4, NB), 256>>>(dft1, SEGsz, 0,
                                             xs, EDsz, (long long)SEGsz * EDsz,
                                             Xf, EDsz, (long long)2 * SEGsz * EDsz, SEGsz);
        czi_k<<<((size_t)NB * SEGsz * EDsz / 4) / 256, 256>>>(Xf, delta, Zb, sig);
        // stage 2: Yf = dft2 @ [Zr; Zi]       (256 x 2048, K=512, batch=32)
        tgemm_nn_k<<<dim3(16, 2, NB), 256>>>(dft2, 2 * SEGsz, 0,
                                             Zb, EDsz, (long long)2 * SEGsz * EDsz,
                                             Yf, EDsz, (long long)SEGsz * EDsz, 2 * SEGsz);

        zero_k<<<(SROWS * EDsz / 4) / 256, 256>>>(K, SROWS * EDsz / 4);

        for (int s = 0; s < NSEG; s++) {
            int s0 = s * SEGsz;

            kerr_k<<<(SROWS * EDsz / 4) / 256, 256>>>(xs, y, keh, s0, s == 0 ? 1 : 0);

            // kproj1: h1 = relu(Kerr @ k1_w^T + b)  (1024 x 6144, K=2048) -> fp16
            ts_gemm_k<1,true><<<dim3(48, 8), 256>>>(
                keh, k1wh, nullptr, h1h, EDsz, EDsz, 3*EDsz, 3*EDsz, EDsz, k1b);
            // kproj2: h2 = relu(h1 @ k2_w^T)        (1024 x 2048, K=6144) -> fp16
            ts_gemm_k<2,true><<<dim3(16, 8), 256>>>(
                h1h, k2wh, nullptr, h2h, 3*EDsz, 3*EDsz, EDsz, EDsz, 3*EDsz, nullptr);
            // kproj3: h3 = h2 @ k3_w^T              (1024 x 2048, K=2048) -> fp32
            ts_gemm_k<0,false><<<dim3(16, 8), 256>>>(
                h2h, k3wh, h3, nullptr, EDsz, EDsz, EDsz, EDsz, EDsz, nullptr);

            kup_k<<<SROWS, 256>>>(h3, lng, lnb, kal, K);

            scan_k<<<Bsz * (EDsz / 128), 128>>>(K, delta, xs, Yf, dC, alg, dpp, y, s0);
        }

        gate_k<<<(MROWS * EDsz / 4) / 256, 256>>>(y, xz, ygh);

        // h += yg @ out_w^T   (8192 x 1024, K=2048)  [accumulate]
        ts_gemm_k<4,false><<<dim3(8, 64), 256>>>(
            ygh, owh, h, nullptr, EDsz, EDsz, DMsz, DMsz, EDsz, nullptr);
    }
}